// round 3
// baseline (speedup 1.0000x reference)
#include <cuda_runtime.h>
#include <cuda_bf16.h>

#define CDIM 1024
#define CS   2048
#define CB   4
#define NH   16
#define HD   64
#define LAT  128
#define QR   256
#define MTOT (CB*CS)   // 8192 tokens

// -------- scratch (static device globals; no runtime allocation) --------
__device__ float g_kvlat[(size_t)MTOT * LAT];        //  4 MB
__device__ float g_kvup [(size_t)MTOT * 2 * CDIM];   // 64 MB (K | V)
__device__ float g_qlat [(size_t)MTOT * QR];         //  8 MB
__device__ float g_q    [(size_t)MTOT * CDIM];       // 32 MB
__device__ float g_ctx  [(size_t)MTOT * CDIM];       // 32 MB

// ---------------------------------------------------------------
// Tiled SGEMM: C[M,N] = A[M,K] @ B[K,N] + bias[N]
// 64x64 block tile, BK=16, 256 threads, 4x4 micro-tile per thread.
// Requires: M%64==0, N%64==0, K%16==0 (true for all 5 calls).
// ---------------------------------------------------------------
__global__ __launch_bounds__(256) void sgemm_bias(
    const float* __restrict__ A, const float* __restrict__ B,
    const float* __restrict__ bias, float* __restrict__ C,
    int M, int N, int K)
{
    const int BK = 16;
    __shared__ float As[16][64];   // transposed: As[k][m]
    __shared__ float Bs[16][64];   // Bs[k][n]

    int tid  = threadIdx.x;
    int row0 = blockIdx.y * 64;
    int col0 = blockIdx.x * 64;

    // A loads: 64x16 floats = 256 float4 (4 consecutive k per thread)
    int aRow = tid >> 2;
    int aCol = (tid & 3) << 2;
    // B loads: 16x64 floats = 256 float4 (4 consecutive n per thread)
    int bRow = tid >> 4;
    int bCol = (tid & 15) << 2;

    int ty = tid >> 4;   // 0..15
    int tx = tid & 15;   // 0..15

    float acc[4][4] = {};

    for (int k0 = 0; k0 < K; k0 += BK) {
        float4 a4 = *(const float4*)(A + (size_t)(row0 + aRow) * K + k0 + aCol);
        As[aCol + 0][aRow] = a4.x;
        As[aCol + 1][aRow] = a4.y;
        As[aCol + 2][aRow] = a4.z;
        As[aCol + 3][aRow] = a4.w;
        *(float4*)(&Bs[bRow][bCol]) =
            *(const float4*)(B + (size_t)(k0 + bRow) * N + col0 + bCol);
        __syncthreads();

#pragma unroll
        for (int k = 0; k < BK; k++) {
            float4 ra = *(const float4*)(&As[k][ty << 2]);
            float4 rb = *(const float4*)(&Bs[k][tx << 2]);
            float av[4] = {ra.x, ra.y, ra.z, ra.w};
            float bv[4] = {rb.x, rb.y, rb.z, rb.w};
#pragma unroll
            for (int i = 0; i < 4; i++)
#pragma unroll
                for (int j = 0; j < 4; j++)
                    acc[i][j] += av[i] * bv[j];
        }
        __syncthreads();
    }

#pragma unroll
    for (int i = 0; i < 4; i++) {
        int r = row0 + (ty << 2) + i;
#pragma unroll
        for (int j = 0; j < 4; j++) {
            int c = col0 + (tx << 2) + j;
            C[(size_t)r * N + c] = acc[i][j] + bias[c];
        }
    }
}

// ---------------------------------------------------------------
// Causal flash attention, fp32.
// grid: (S/64, B*H); block: 64 threads; thread t owns query row q0+t.
// Q layout: [B,S,DIM] with head h at cols h*64..h*64+63.
// KV layout: [B,S,2*DIM]; K at col h*64, V at col 1024 + h*64.
// Writes ctx in [B,S,DIM] token-major layout (ready for final GEMM).
// ---------------------------------------------------------------
__global__ __launch_bounds__(64) void flash_attn(
    const float* __restrict__ Qm, const float* __restrict__ KV,
    float* __restrict__ ctx)
{
    int bh = blockIdx.y;
    int b  = bh >> 4;
    int h  = bh & 15;
    int q0 = blockIdx.x * 64;
    int tid = threadIdx.x;
    int s_q = q0 + tid;

    // q row into registers
    const float* qptr = Qm + ((size_t)(b * CS + s_q)) * CDIM + h * HD;
    float q[64];
#pragma unroll
    for (int i = 0; i < 16; i++) {
        float4 v = *(const float4*)(qptr + i * 4);
        q[i*4+0] = v.x; q[i*4+1] = v.y; q[i*4+2] = v.z; q[i*4+3] = v.w;
    }

    float o[64];
#pragma unroll
    for (int d = 0; d < 64; d++) o[d] = 0.f;
    float m = -1e30f, l = 0.f;

    __shared__ float Ks[16][64];
    __shared__ float Vs[16][64];

    int nkt = (q0 + 64) >> 4;   // key tiles covering keys 0..q0+63
    for (int kt = 0; kt < nkt; kt++) {
        int k0 = kt << 4;
        // cooperative load of 16x64 K and V tiles (float4 granularity)
        for (int i = tid; i < 256; i += 64) {
            int r = i >> 4;
            int c = (i & 15) << 2;
            const float* base = KV + ((size_t)(b * CS + k0 + r)) * (2 * CDIM) + h * HD;
            *(float4*)&Ks[r][c] = *(const float4*)(base + c);
            *(float4*)&Vs[r][c] = *(const float4*)(base + CDIM + c);
        }
        __syncthreads();

        float s[16];
        float tmax = -1e30f;
#pragma unroll
        for (int j = 0; j < 16; j++) {
            float acc = 0.f;
#pragma unroll
            for (int d4 = 0; d4 < 16; d4++) {
                float4 kx = *(const float4*)(&Ks[j][d4 << 2]);
                acc += q[d4*4+0] * kx.x + q[d4*4+1] * kx.y
                     + q[d4*4+2] * kx.z + q[d4*4+3] * kx.w;
            }
            s[j] = (k0 + j <= s_q) ? acc * 0.125f : -1e30f;
            tmax = fmaxf(tmax, s[j]);
        }

        float m_new = fmaxf(m, tmax);
        float corr  = __expf(m - m_new);
        l *= corr;
#pragma unroll
        for (int d = 0; d < 64; d++) o[d] *= corr;

#pragma unroll
        for (int j = 0; j < 16; j++) {
            float p = __expf(s[j] - m_new);
            l += p;
#pragma unroll
            for (int d4 = 0; d4 < 16; d4++) {
                float4 vx = *(const float4*)(&Vs[j][d4 << 2]);
                o[d4*4+0] += p * vx.x;
                o[d4*4+1] += p * vx.y;
                o[d4*4+2] += p * vx.z;
                o[d4*4+3] += p * vx.w;
            }
        }
        m = m_new;
        __syncthreads();
    }

    float inv = 1.f / l;
    float* op = ctx + ((size_t)(b * CS + s_q)) * CDIM + h * HD;
#pragma unroll
    for (int i = 0; i < 16; i++) {
        float4 v;
        v.x = o[i*4+0] * inv; v.y = o[i*4+1] * inv;
        v.z = o[i*4+2] * inv; v.w = o[i*4+3] * inv;
        *(float4*)(op + i * 4) = v;
    }
}

// ---------------------------------------------------------------
extern "C" void kernel_launch(void* const* d_in, const int* in_sizes, int n_in,
                              void* d_out, int out_size)
{
    const float* x      = (const float*)d_in[0];
    // d_in[1] = causal mask (tril), implemented analytically in flash_attn
    const float* w_kvc  = (const float*)d_in[2];
    const float* b_kvc  = (const float*)d_in[3];
    const float* w_kvu  = (const float*)d_in[4];
    const float* b_kvu  = (const float*)d_in[5];
    const float* w_qc   = (const float*)d_in[6];
    const float* b_qc   = (const float*)d_in[7];
    const float* w_qu   = (const float*)d_in[8];
    const float* b_qu   = (const float*)d_in[9];
    const float* w_o    = (const float*)d_in[10];
    const float* b_o    = (const float*)d_in[11];
    float* out = (float*)d_out;

    float *kvlat, *kvup, *qlat, *Qm, *ctx;
    cudaGetSymbolAddress((void**)&kvlat, g_kvlat);
    cudaGetSymbolAddress((void**)&kvup,  g_kvup);
    cudaGetSymbolAddress((void**)&qlat,  g_qlat);
    cudaGetSymbolAddress((void**)&Qm,    g_q);
    cudaGetSymbolAddress((void**)&ctx,   g_ctx);

    // 1) kv_latent = x @ w_kvc + b_kvc            [8192,128]
    sgemm_bias<<<dim3(LAT/64,      MTOT/64), 256>>>(x,     w_kvc, b_kvc, kvlat, MTOT, LAT,     CDIM);
    // 2) kv_up = kv_latent @ w_kvu + b_kvu        [8192,2048]  (K | V)
    sgemm_bias<<<dim3(2*CDIM/64,   MTOT/64), 256>>>(kvlat, w_kvu, b_kvu, kvup,  MTOT, 2*CDIM,  LAT);
    // 3) q_lat = x @ w_qc + b_qc                  [8192,256]
    sgemm_bias<<<dim3(QR/64,       MTOT/64), 256>>>(x,     w_qc,  b_qc,  qlat,  MTOT, QR,      CDIM);
    // 4) Q = q_lat @ w_qu + b_qu                  [8192,1024]
    sgemm_bias<<<dim3(CDIM/64,     MTOT/64), 256>>>(qlat,  w_qu,  b_qu,  Qm,    MTOT, CDIM,    QR);
    // 5) causal flash attention -> ctx            [8192,1024]
    flash_attn<<<dim3(CS/64, CB*NH), 64>>>(Qm, kvup, ctx);
    // 6) out = ctx @ w_o + b_o                    [8192,1024]
    sgemm_bias<<<dim3(CDIM/64,     MTOT/64), 256>>>(ctx,   w_o,   b_o,   out,   MTOT, CDIM,    CDIM);
}

// round 4
// speedup vs baseline: 1.9928x; 1.9928x over previous
#include <cuda_runtime.h>
#include <cuda_bf16.h>
#include <cstdint>

#define CDIM 1024
#define CS   2048
#define CB   4
#define NH   16
#define HD   64
#define LAT  128
#define QR   256
#define MTOT (CB*CS)   // 8192 tokens

// -------- scratch (static device globals; no runtime allocation) --------
__device__ float g_kvlat[(size_t)MTOT * LAT];        //  4 MB
__device__ float g_kvup [(size_t)MTOT * 2 * CDIM];   // 64 MB (K | V)
__device__ float g_qlat [(size_t)MTOT * QR];         //  8 MB
__device__ float g_q    [(size_t)MTOT * CDIM];       // 32 MB
__device__ float g_ctx  [(size_t)MTOT * CDIM];       // 32 MB

// ---------------------------------------------------------------
// Tiled SGEMM: C[M,N] = A[M,K] @ B[K,N] + bias[N]   (unchanged, proven)
// ---------------------------------------------------------------
__global__ __launch_bounds__(256) void sgemm_bias(
    const float* __restrict__ A, const float* __restrict__ B,
    const float* __restrict__ bias, float* __restrict__ C,
    int M, int N, int K)
{
    const int BK = 16;
    __shared__ float As[16][64];
    __shared__ float Bs[16][64];

    int tid  = threadIdx.x;
    int row0 = blockIdx.y * 64;
    int col0 = blockIdx.x * 64;

    int aRow = tid >> 2;
    int aCol = (tid & 3) << 2;
    int bRow = tid >> 4;
    int bCol = (tid & 15) << 2;

    int ty = tid >> 4;
    int tx = tid & 15;

    float acc[4][4] = {};

    for (int k0 = 0; k0 < K; k0 += BK) {
        float4 a4 = *(const float4*)(A + (size_t)(row0 + aRow) * K + k0 + aCol);
        As[aCol + 0][aRow] = a4.x;
        As[aCol + 1][aRow] = a4.y;
        As[aCol + 2][aRow] = a4.z;
        As[aCol + 3][aRow] = a4.w;
        *(float4*)(&Bs[bRow][bCol]) =
            *(const float4*)(B + (size_t)(k0 + bRow) * N + col0 + bCol);
        __syncthreads();

#pragma unroll
        for (int k = 0; k < BK; k++) {
            float4 ra = *(const float4*)(&As[k][ty << 2]);
            float4 rb = *(const float4*)(&Bs[k][tx << 2]);
            float av[4] = {ra.x, ra.y, ra.z, ra.w};
            float bv[4] = {rb.x, rb.y, rb.z, rb.w};
#pragma unroll
            for (int i = 0; i < 4; i++)
#pragma unroll
                for (int j = 0; j < 4; j++)
                    acc[i][j] += av[i] * bv[j];
        }
        __syncthreads();
    }

#pragma unroll
    for (int i = 0; i < 4; i++) {
        int r = row0 + (ty << 2) + i;
#pragma unroll
        for (int j = 0; j < 4; j++) {
            int c = col0 + (tx << 2) + j;
            C[(size_t)r * N + c] = acc[i][j] + bias[c];
        }
    }
}

// ---------------------------------------------------------------
// bf16 tensor-core helpers
// ---------------------------------------------------------------
__device__ __forceinline__ void mma_bf16(float d[4], const uint32_t a[4],
                                         const uint32_t b[2])
{
    asm volatile(
        "mma.sync.aligned.m16n8k16.row.col.f32.bf16.bf16.f32 "
        "{%0,%1,%2,%3}, {%4,%5,%6,%7}, {%8,%9}, {%0,%1,%2,%3};\n"
        : "+f"(d[0]), "+f"(d[1]), "+f"(d[2]), "+f"(d[3])
        : "r"(a[0]), "r"(a[1]), "r"(a[2]), "r"(a[3]),
          "r"(b[0]), "r"(b[1]));
}

// pack two floats -> bf16x2 register, first arg in low half
__device__ __forceinline__ uint32_t pack_bf16(float lo, float hi)
{
    uint32_t r;
    asm("cvt.rn.bf16x2.f32 %0, %2, %1;" : "=r"(r) : "f"(lo), "f"(hi));
    return r;
}

__device__ __forceinline__ uint32_t hpair(__nv_bfloat16 lo, __nv_bfloat16 hi)
{
    __nv_bfloat162 v;
    v.x = lo; v.y = hi;
    return *(uint32_t*)&v;
}

// ---------------------------------------------------------------
// Causal flash attention on tensor cores (mma.sync bf16).
// grid: (S/128, B*H); block 256 (8 warps). Warp w owns 16 query rows.
// Key tiles of 64. QK^T plain bf16 (scores are tiny; softmax washes it).
// P.V with hi/lo bf16 split of BOTH P and V (3 mma passes) for precision.
// Smem rows padded to 72 bf16 (144B) -> all fragment LDS conflict-free.
// ---------------------------------------------------------------
__global__ __launch_bounds__(256) void flash_attn_mma(
    const float* __restrict__ Qm, const float* __restrict__ KV,
    float* __restrict__ ctx)
{
    __shared__ __nv_bfloat16 Ks  [64][72];
    __shared__ __nv_bfloat16 Vthi[64][72];   // V transposed: [dim][key]
    __shared__ __nv_bfloat16 Vtlo[64][72];

    const int bh = blockIdx.y;
    const int b  = bh >> 4;
    const int h  = bh & 15;
    const int q0 = blockIdx.x * 128;
    const int tid  = threadIdx.x;
    const int w    = tid >> 5;
    const int lane = tid & 31;
    const int g    = lane >> 2;   // 0..7
    const int t    = lane & 3;    // 0..3
    const int qb   = q0 + w * 16; // first query row of this warp

    // ---- Q fragments (scale 1/sqrt(64)=0.125 folded in) ----
    uint32_t Qf[4][4];
    {
        const float* q0p = Qm + ((size_t)(b * CS + qb + g)) * CDIM + h * HD;
        const float* q1p = q0p + 8 * (size_t)CDIM;
        const float sc = 0.125f;
#pragma unroll
        for (int kk = 0; kk < 4; kk++) {
            int c = kk * 16 + 2 * t;
            Qf[kk][0] = pack_bf16(q0p[c]     * sc, q0p[c + 1] * sc);
            Qf[kk][1] = pack_bf16(q1p[c]     * sc, q1p[c + 1] * sc);
            Qf[kk][2] = pack_bf16(q0p[c + 8] * sc, q0p[c + 9] * sc);
            Qf[kk][3] = pack_bf16(q1p[c + 8] * sc, q1p[c + 9] * sc);
        }
    }

    float O[8][4];
#pragma unroll
    for (int i = 0; i < 8; i++)
#pragma unroll
        for (int j = 0; j < 4; j++) O[i][j] = 0.f;
    float m0 = -1e30f, m1 = -1e30f, l0 = 0.f, l1 = 0.f;

    const int nkt = (q0 + 128) / 64;   // causal extent in 64-key tiles

    for (int kt = 0; kt < nkt; kt++) {
        // ---- cooperative tile load: K -> Ks, V -> Vthi/Vtlo (transposed) ----
        const float* base = KV + ((size_t)(b * CS + kt * 64)) * (2 * CDIM) + h * HD;
#pragma unroll
        for (int it = 0; it < 4; it++) {
            int i = tid + it * 256;
            int r = i >> 4;            // key row 0..63
            int c = (i & 15) * 4;      // dim col 0..60
            const float* kp = base + (size_t)r * (2 * CDIM) + c;
            float4 kv = *(const float4*)kp;
            __nv_bfloat162* ksp = (__nv_bfloat162*)&Ks[r][c];
            ksp[0] = __floats2bfloat162_rn(kv.x, kv.y);
            ksp[1] = __floats2bfloat162_rn(kv.z, kv.w);
            float4 vv = *(const float4*)(kp + CDIM);
            float vf[4] = {vv.x, vv.y, vv.z, vv.w};
#pragma unroll
            for (int cc = 0; cc < 4; cc++) {
                __nv_bfloat16 hi = __float2bfloat16(vf[cc]);
                Vthi[c + cc][r] = hi;
                Vtlo[c + cc][r] = __float2bfloat16(vf[cc] - __bfloat162float(hi));
            }
        }
        __syncthreads();

        if (kt * 64 <= qb + 15) {      // tile not fully above the diagonal
            // ---- S = Q K^T ----
            float S[8][4];
#pragma unroll
            for (int j = 0; j < 8; j++) {
                S[j][0] = S[j][1] = S[j][2] = S[j][3] = 0.f;
#pragma unroll
                for (int kk = 0; kk < 4; kk++) {
                    uint32_t Bk[2];
                    const __nv_bfloat16* kr = &Ks[j * 8 + g][kk * 16 + 2 * t];
                    Bk[0] = *(const uint32_t*)kr;
                    Bk[1] = *(const uint32_t*)(kr + 8);
                    mma_bf16(S[j], Qf[kk], Bk);
                }
            }
            // ---- causal mask (diagonal tiles only) ----
            if (kt * 64 + 63 > qb) {
#pragma unroll
                for (int j = 0; j < 8; j++) {
                    int key = kt * 64 + j * 8 + 2 * t;
                    if (key     > qb + g)     S[j][0] = -1e30f;
                    if (key + 1 > qb + g)     S[j][1] = -1e30f;
                    if (key     > qb + g + 8) S[j][2] = -1e30f;
                    if (key + 1 > qb + g + 8) S[j][3] = -1e30f;
                }
            }
            // ---- online softmax (rows g and g+8) ----
            float rmax0 = -1e30f, rmax1 = -1e30f;
#pragma unroll
            for (int j = 0; j < 8; j++) {
                rmax0 = fmaxf(rmax0, fmaxf(S[j][0], S[j][1]));
                rmax1 = fmaxf(rmax1, fmaxf(S[j][2], S[j][3]));
            }
#pragma unroll
            for (int off = 1; off <= 2; off <<= 1) {
                rmax0 = fmaxf(rmax0, __shfl_xor_sync(0xffffffffu, rmax0, off));
                rmax1 = fmaxf(rmax1, __shfl_xor_sync(0xffffffffu, rmax1, off));
            }
            float mn0 = fmaxf(m0, rmax0), mn1 = fmaxf(m1, rmax1);
            float sc0 = __expf(m0 - mn0), sc1 = __expf(m1 - mn1);
            float ls0 = 0.f, ls1 = 0.f;
#pragma unroll
            for (int j = 0; j < 8; j++) {
                S[j][0] = __expf(S[j][0] - mn0); ls0 += S[j][0];
                S[j][1] = __expf(S[j][1] - mn0); ls0 += S[j][1];
                S[j][2] = __expf(S[j][2] - mn1); ls1 += S[j][2];
                S[j][3] = __expf(S[j][3] - mn1); ls1 += S[j][3];
            }
#pragma unroll
            for (int off = 1; off <= 2; off <<= 1) {
                ls0 += __shfl_xor_sync(0xffffffffu, ls0, off);
                ls1 += __shfl_xor_sync(0xffffffffu, ls1, off);
            }
            l0 = l0 * sc0 + ls0;
            l1 = l1 * sc1 + ls1;
            m0 = mn0; m1 = mn1;
#pragma unroll
            for (int nj = 0; nj < 8; nj++) {
                O[nj][0] *= sc0; O[nj][1] *= sc0;
                O[nj][2] *= sc1; O[nj][3] *= sc1;
            }
            // ---- O += P V  (hi/lo split of P and V: 3 mma passes) ----
#pragma unroll
            for (int s = 0; s < 4; s++) {
                uint32_t Ah[4], Al[4];
#pragma unroll
                for (int r = 0; r < 4; r++) {
                    int jt = 2 * s + (r >> 1);
                    float x = S[jt][(r & 1) * 2 + 0];
                    float y = S[jt][(r & 1) * 2 + 1];
                    __nv_bfloat16 hx = __float2bfloat16(x);
                    __nv_bfloat16 hy = __float2bfloat16(y);
                    Ah[r] = hpair(hx, hy);
                    Al[r] = hpair(__float2bfloat16(x - __bfloat162float(hx)),
                                  __float2bfloat16(y - __bfloat162float(hy)));
                }
#pragma unroll
                for (int nj = 0; nj < 8; nj++) {
                    uint32_t Bh[2], Bl[2];
                    const __nv_bfloat16* vh = &Vthi[nj * 8 + g][s * 16 + 2 * t];
                    const __nv_bfloat16* vl = &Vtlo[nj * 8 + g][s * 16 + 2 * t];
                    Bh[0] = *(const uint32_t*)vh;
                    Bh[1] = *(const uint32_t*)(vh + 8);
                    Bl[0] = *(const uint32_t*)vl;
                    Bl[1] = *(const uint32_t*)(vl + 8);
                    mma_bf16(O[nj], Ah, Bh);
                    mma_bf16(O[nj], Ah, Bl);
                    mma_bf16(O[nj], Al, Bh);
                }
            }
        }
        __syncthreads();
    }

    // ---- epilogue: normalize and write ctx ----
    float inv0 = 1.f / l0, inv1 = 1.f / l1;
    float* op0 = ctx + ((size_t)(b * CS + qb + g)) * CDIM + h * HD;
    float* op1 = op0 + 8 * (size_t)CDIM;
#pragma unroll
    for (int nj = 0; nj < 8; nj++) {
        int c = nj * 8 + 2 * t;
        op0[c]     = O[nj][0] * inv0;
        op0[c + 1] = O[nj][1] * inv0;
        op1[c]     = O[nj][2] * inv1;
        op1[c + 1] = O[nj][3] * inv1;
    }
}

// ---------------------------------------------------------------
extern "C" void kernel_launch(void* const* d_in, const int* in_sizes, int n_in,
                              void* d_out, int out_size)
{
    const float* x      = (const float*)d_in[0];
    // d_in[1] = causal mask (tril), implemented analytically in flash_attn_mma
    const float* w_kvc  = (const float*)d_in[2];
    const float* b_kvc  = (const float*)d_in[3];
    const float* w_kvu  = (const float*)d_in[4];
    const float* b_kvu  = (const float*)d_in[5];
    const float* w_qc   = (const float*)d_in[6];
    const float* b_qc   = (const float*)d_in[7];
    const float* w_qu   = (const float*)d_in[8];
    const float* b_qu   = (const float*)d_in[9];
    const float* w_o    = (const float*)d_in[10];
    const float* b_o    = (const float*)d_in[11];
    float* out = (float*)d_out;

    float *kvlat, *kvup, *qlat, *Qm, *ctx;
    cudaGetSymbolAddress((void**)&kvlat, g_kvlat);
    cudaGetSymbolAddress((void**)&kvup,  g_kvup);
    cudaGetSymbolAddress((void**)&qlat,  g_qlat);
    cudaGetSymbolAddress((void**)&Qm,    g_q);
    cudaGetSymbolAddress((void**)&ctx,   g_ctx);

    // 1) kv_latent = x @ w_kvc + b_kvc            [8192,128]
    sgemm_bias<<<dim3(LAT/64,      MTOT/64), 256>>>(x,     w_kvc, b_kvc, kvlat, MTOT, LAT,     CDIM);
    // 2) kv_up = kv_latent @ w_kvu + b_kvu        [8192,2048]  (K | V)
    sgemm_bias<<<dim3(2*CDIM/64,   MTOT/64), 256>>>(kvlat, w_kvu, b_kvu, kvup,  MTOT, 2*CDIM,  LAT);
    // 3) q_lat = x @ w_qc + b_qc                  [8192,256]
    sgemm_bias<<<dim3(QR/64,       MTOT/64), 256>>>(x,     w_qc,  b_qc,  qlat,  MTOT, QR,      CDIM);
    // 4) Q = q_lat @ w_qu + b_qu                  [8192,1024]
    sgemm_bias<<<dim3(CDIM/64,     MTOT/64), 256>>>(qlat,  w_qu,  b_qu,  Qm,    MTOT, CDIM,    QR);
    // 5) causal flash attention (tensor cores) -> ctx
    flash_attn_mma<<<dim3(CS/128, CB*NH), 256>>>(Qm, kvup, ctx);
    // 6) out = ctx @ w_o + b_o                    [8192,1024]
    sgemm_bias<<<dim3(CDIM/64,     MTOT/64), 256>>>(ctx,   w_o,   b_o,   out,   MTOT, CDIM,    CDIM);
}

// round 6
// speedup vs baseline: 3.3952x; 1.7038x over previous
#include <cuda_runtime.h>
#include <cuda_bf16.h>
#include <cstdint>

#define CDIM 1024
#define CS   2048
#define CB   4
#define NH   16
#define HD   64
#define LAT  128
#define QR   256
#define MTOT (CB*CS)   // 8192 tokens

// -------- scratch (static device globals; no runtime allocation) --------
__device__ float g_kvlat[(size_t)MTOT * LAT];        //  4 MB
__device__ float g_kvup [(size_t)MTOT * 2 * CDIM];   // 64 MB (K | V)
__device__ float g_qlat [(size_t)MTOT * QR];         //  8 MB
__device__ float g_q    [(size_t)MTOT * CDIM];       // 32 MB
__device__ float g_ctx  [(size_t)MTOT * CDIM];       // 32 MB

// ---------------------------------------------------------------
// common helpers
// ---------------------------------------------------------------
__device__ __forceinline__ void mma_bf16(float d[4], const uint32_t a[4],
                                         const uint32_t b[2])
{
    asm volatile(
        "mma.sync.aligned.m16n8k16.row.col.f32.bf16.bf16.f32 "
        "{%0,%1,%2,%3}, {%4,%5,%6,%7}, {%8,%9}, {%0,%1,%2,%3};\n"
        : "+f"(d[0]), "+f"(d[1]), "+f"(d[2]), "+f"(d[3])
        : "r"(a[0]), "r"(a[1]), "r"(a[2]), "r"(a[3]),
          "r"(b[0]), "r"(b[1]));
}

__device__ __forceinline__ uint32_t pack_bf16(float lo, float hi)
{
    uint32_t r;
    asm("cvt.rn.bf16x2.f32 %0, %2, %1;" : "=r"(r) : "f"(lo), "f"(hi));
    return r;
}

__device__ __forceinline__ uint32_t hpair(__nv_bfloat16 lo, __nv_bfloat16 hi)
{
    __nv_bfloat162 v;
    v.x = lo; v.y = hi;
    return *(uint32_t*)&v;
}

__device__ __forceinline__ void ldsm_x4(uint32_t r[4], const void* p)
{
    uint32_t a = (uint32_t)__cvta_generic_to_shared(p);
    asm volatile("ldmatrix.sync.aligned.m8n8.x4.shared.b16 {%0,%1,%2,%3}, [%4];"
                 : "=r"(r[0]), "=r"(r[1]), "=r"(r[2]), "=r"(r[3]) : "r"(a));
}

__device__ __forceinline__ void ldsm_x4_t(uint32_t r[4], const void* p)
{
    uint32_t a = (uint32_t)__cvta_generic_to_shared(p);
    asm volatile("ldmatrix.sync.aligned.m8n8.x4.trans.shared.b16 {%0,%1,%2,%3}, [%4];"
                 : "=r"(r[0]), "=r"(r[1]), "=r"(r[2]), "=r"(r[3]) : "r"(a));
}

// ---------------------------------------------------------------
// Tensor-core GEMM with bf16 hi/lo 3-pass split (fp32-accurate).
// C[M,N] = A[M,K] @ B[K,N] + bias[N]
// CTA tile 128x128, BK=32, 8 warps (warp tile 64x32).
// A smem [m][k] pitch 40 (LDSM conflict-free), B smem [k][n] pitch 136,
// transposed in-flight via ldmatrix.trans.
// Requires M%128==0, N%128==0, K%32==0.
// ---------------------------------------------------------------
#define APITCH 40
#define BPITCH 136

__global__ __launch_bounds__(256, 1) void hgemm_bias(
    const float* __restrict__ A, const float* __restrict__ B,
    const float* __restrict__ bias, float* __restrict__ C,
    int M, int N, int K)
{
    __shared__ __align__(16) __nv_bfloat16 Ahs[128 * APITCH];
    __shared__ __align__(16) __nv_bfloat16 Als[128 * APITCH];
    __shared__ __align__(16) __nv_bfloat16 Bhs[32 * BPITCH];
    __shared__ __align__(16) __nv_bfloat16 Bls[32 * BPITCH];

    const int tid  = threadIdx.x;
    const int w    = tid >> 5;
    const int lane = tid & 31;
    const int wm   = w >> 2;      // 0..1
    const int wn   = w & 3;       // 0..3
    const int m0   = wm * 64;
    const int n0   = wn * 32;
    const int row0 = blockIdx.y * 128;
    const int col0 = blockIdx.x * 128;

    float Cacc[4][4][4] = {};
    float4 aR[4], bR[4];

    auto ldTiles = [&](int k0) {
#pragma unroll
        for (int i = 0; i < 4; i++) {
            int f = tid + i * 256;
            int r = f >> 3, c = (f & 7) << 2;
            aR[i] = *(const float4*)(A + (size_t)(row0 + r) * K + k0 + c);
        }
#pragma unroll
        for (int i = 0; i < 4; i++) {
            int f = tid + i * 256;
            int r = f >> 5, c = (f & 31) << 2;
            bR[i] = *(const float4*)(B + (size_t)(k0 + r) * N + col0 + c);
        }
    };

    auto stTiles = [&]() {
#pragma unroll
        for (int i = 0; i < 4; i++) {
            int f = tid + i * 256;
            int r = f >> 3, c = (f & 7) << 2;
            float v[4] = {aR[i].x, aR[i].y, aR[i].z, aR[i].w};
#pragma unroll
            for (int j = 0; j < 2; j++) {
                __nv_bfloat16 h0 = __float2bfloat16(v[2 * j]);
                __nv_bfloat16 h1 = __float2bfloat16(v[2 * j + 1]);
                *(uint32_t*)&Ahs[r * APITCH + c + 2 * j] = hpair(h0, h1);
                *(uint32_t*)&Als[r * APITCH + c + 2 * j] =
                    hpair(__float2bfloat16(v[2 * j]     - __bfloat162float(h0)),
                          __float2bfloat16(v[2 * j + 1] - __bfloat162float(h1)));
            }
        }
#pragma unroll
        for (int i = 0; i < 4; i++) {
            int f = tid + i * 256;
            int r = f >> 5, c = (f & 31) << 2;
            float v[4] = {bR[i].x, bR[i].y, bR[i].z, bR[i].w};
#pragma unroll
            for (int j = 0; j < 2; j++) {
                __nv_bfloat16 h0 = __float2bfloat16(v[2 * j]);
                __nv_bfloat16 h1 = __float2bfloat16(v[2 * j + 1]);
                *(uint32_t*)&Bhs[r * BPITCH + c + 2 * j] = hpair(h0, h1);
                *(uint32_t*)&Bls[r * BPITCH + c + 2 * j] =
                    hpair(__float2bfloat16(v[2 * j]     - __bfloat162float(h0)),
                          __float2bfloat16(v[2 * j + 1] - __bfloat162float(h1)));
            }
        }
    };

    ldTiles(0);
    stTiles();
    __syncthreads();

    const int nk = K >> 5;
    for (int it = 0; it < nk; it++) {
        const int k0 = (it + 1) << 5;
        const bool more = k0 < K;
        if (more) ldTiles(k0);

        // ---- compute from smem ----
#pragma unroll
        for (int ks = 0; ks < 2; ks++) {
            uint32_t Af[4][4], Alf[4][4];
#pragma unroll
            for (int mi = 0; mi < 4; mi++) {
                int idx = (m0 + mi * 16 + (lane & 15)) * APITCH
                        + ks * 16 + ((lane >> 4) << 3);
                ldsm_x4(Af[mi],  &Ahs[idx]);
                ldsm_x4(Alf[mi], &Als[idx]);
            }
            uint32_t Bf[4][2], Blf[4][2];
#pragma unroll
            for (int nj = 0; nj < 2; nj++) {
                int rrow = ks * 16 + ((lane >> 3) & 1) * 8 + (lane & 7);
                int ccol = n0 + nj * 16 + ((lane >> 4) << 3);
                uint32_t t4[4];
                ldsm_x4_t(t4, &Bhs[rrow * BPITCH + ccol]);
                Bf[nj * 2][0] = t4[0]; Bf[nj * 2][1] = t4[1];
                Bf[nj * 2 + 1][0] = t4[2]; Bf[nj * 2 + 1][1] = t4[3];
                ldsm_x4_t(t4, &Bls[rrow * BPITCH + ccol]);
                Blf[nj * 2][0] = t4[0]; Blf[nj * 2][1] = t4[1];
                Blf[nj * 2 + 1][0] = t4[2]; Blf[nj * 2 + 1][1] = t4[3];
            }
#pragma unroll
            for (int mi = 0; mi < 4; mi++)
#pragma unroll
                for (int nf = 0; nf < 4; nf++) {
                    mma_bf16(Cacc[mi][nf], Af[mi],  Bf[nf]);
                    mma_bf16(Cacc[mi][nf], Af[mi],  Blf[nf]);
                    mma_bf16(Cacc[mi][nf], Alf[mi], Bf[nf]);
                }
        }
        __syncthreads();
        if (more) {
            stTiles();
            __syncthreads();
        }
    }

    // ---- epilogue ----
    const int g = lane >> 2, t = lane & 3;
#pragma unroll
    for (int mi = 0; mi < 4; mi++) {
#pragma unroll
        for (int nf = 0; nf < 4; nf++) {
            int gr = row0 + m0 + mi * 16 + g;
            int gc = col0 + n0 + nf * 8 + 2 * t;
            float b0 = bias[gc], b1 = bias[gc + 1];
            float2 v0 = {Cacc[mi][nf][0] + b0, Cacc[mi][nf][1] + b1};
            float2 v1 = {Cacc[mi][nf][2] + b0, Cacc[mi][nf][3] + b1};
            *(float2*)&C[(size_t)gr * N + gc] = v0;
            *(float2*)&C[(size_t)(gr + 8) * N + gc] = v1;
        }
    }
}

// ---------------------------------------------------------------
// Causal flash attention on tensor cores (unchanged from R4, proven).
// ---------------------------------------------------------------
__global__ __launch_bounds__(256) void flash_attn_mma(
    const float* __restrict__ Qm, const float* __restrict__ KV,
    float* __restrict__ ctx)
{
    __shared__ __nv_bfloat16 Ks  [64][72];
    __shared__ __nv_bfloat16 Vthi[64][72];
    __shared__ __nv_bfloat16 Vtlo[64][72];

    const int bh = blockIdx.y;
    const int b  = bh >> 4;
    const int h  = bh & 15;
    const int q0 = blockIdx.x * 128;
    const int tid  = threadIdx.x;
    const int w    = tid >> 5;
    const int lane = tid & 31;
    const int g    = lane >> 2;
    const int t    = lane & 3;
    const int qb   = q0 + w * 16;

    uint32_t Qf[4][4];
    {
        const float* q0p = Qm + ((size_t)(b * CS + qb + g)) * CDIM + h * HD;
        const float* q1p = q0p + 8 * (size_t)CDIM;
        const float sc = 0.125f;
#pragma unroll
        for (int kk = 0; kk < 4; kk++) {
            int c = kk * 16 + 2 * t;
            Qf[kk][0] = pack_bf16(q0p[c]     * sc, q0p[c + 1] * sc);
            Qf[kk][1] = pack_bf16(q1p[c]     * sc, q1p[c + 1] * sc);
            Qf[kk][2] = pack_bf16(q0p[c + 8] * sc, q0p[c + 9] * sc);
            Qf[kk][3] = pack_bf16(q1p[c + 8] * sc, q1p[c + 9] * sc);
        }
    }

    float O[8][4];
#pragma unroll
    for (int i = 0; i < 8; i++)
#pragma unroll
        for (int j = 0; j < 4; j++) O[i][j] = 0.f;
    float m0 = -1e30f, m1 = -1e30f, l0 = 0.f, l1 = 0.f;

    const int nkt = (q0 + 128) / 64;

    for (int kt = 0; kt < nkt; kt++) {
        const float* base = KV + ((size_t)(b * CS + kt * 64)) * (2 * CDIM) + h * HD;
#pragma unroll
        for (int it = 0; it < 4; it++) {
            int i = tid + it * 256;
            int r = i >> 4;
            int c = (i & 15) * 4;
            const float* kp = base + (size_t)r * (2 * CDIM) + c;
            float4 kv = *(const float4*)kp;
            __nv_bfloat162* ksp = (__nv_bfloat162*)&Ks[r][c];
            ksp[0] = __floats2bfloat162_rn(kv.x, kv.y);
            ksp[1] = __floats2bfloat162_rn(kv.z, kv.w);
            float4 vv = *(const float4*)(kp + CDIM);
            float vf[4] = {vv.x, vv.y, vv.z, vv.w};
#pragma unroll
            for (int cc = 0; cc < 4; cc++) {
                __nv_bfloat16 hi = __float2bfloat16(vf[cc]);
                Vthi[c + cc][r] = hi;
                Vtlo[c + cc][r] = __float2bfloat16(vf[cc] - __bfloat162float(hi));
            }
        }
        __syncthreads();

        if (kt * 64 <= qb + 15) {
            float S[8][4];
#pragma unroll
            for (int j = 0; j < 8; j++) {
                S[j][0] = S[j][1] = S[j][2] = S[j][3] = 0.f;
#pragma unroll
                for (int kk = 0; kk < 4; kk++) {
                    uint32_t Bk[2];
                    const __nv_bfloat16* kr = &Ks[j * 8 + g][kk * 16 + 2 * t];
                    Bk[0] = *(const uint32_t*)kr;
                    Bk[1] = *(const uint32_t*)(kr + 8);
                    mma_bf16(S[j], Qf[kk], Bk);
                }
            }
            if (kt * 64 + 63 > qb) {
#pragma unroll
                for (int j = 0; j < 8; j++) {
                    int key = kt * 64 + j * 8 + 2 * t;
                    if (key     > qb + g)     S[j][0] = -1e30f;
                    if (key + 1 > qb + g)     S[j][1] = -1e30f;
                    if (key     > qb + g + 8) S[j][2] = -1e30f;
                    if (key + 1 > qb + g + 8) S[j][3] = -1e30f;
                }
            }
            float rmax0 = -1e30f, rmax1 = -1e30f;
#pragma unroll
            for (int j = 0; j < 8; j++) {
                rmax0 = fmaxf(rmax0, fmaxf(S[j][0], S[j][1]));
                rmax1 = fmaxf(rmax1, fmaxf(S[j][2], S[j][3]));
            }
#pragma unroll
            for (int off = 1; off <= 2; off <<= 1) {
                rmax0 = fmaxf(rmax0, __shfl_xor_sync(0xffffffffu, rmax0, off));
                rmax1 = fmaxf(rmax1, __shfl_xor_sync(0xffffffffu, rmax1, off));
            }
            float mn0 = fmaxf(m0, rmax0), mn1 = fmaxf(m1, rmax1);
            float sc0 = __expf(m0 - mn0), sc1 = __expf(m1 - mn1);
            float ls0 = 0.f, ls1 = 0.f;
#pragma unroll
            for (int j = 0; j < 8; j++) {
                S[j][0] = __expf(S[j][0] - mn0); ls0 += S[j][0];
                S[j][1] = __expf(S[j][1] - mn0); ls0 += S[j][1];
                S[j][2] = __expf(S[j][2] - mn1); ls1 += S[j][2];
                S[j][3] = __expf(S[j][3] - mn1); ls1 += S[j][3];
            }
#pragma unroll
            for (int off = 1; off <= 2; off <<= 1) {
                ls0 += __shfl_xor_sync(0xffffffffu, ls0, off);
                ls1 += __shfl_xor_sync(0xffffffffu, ls1, off);
            }
            l0 = l0 * sc0 + ls0;
            l1 = l1 * sc1 + ls1;
            m0 = mn0; m1 = mn1;
#pragma unroll
            for (int nj = 0; nj < 8; nj++) {
                O[nj][0] *= sc0; O[nj][1] *= sc0;
                O[nj][2] *= sc1; O[nj][3] *= sc1;
            }
#pragma unroll
            for (int s = 0; s < 4; s++) {
                uint32_t Ah[4], Al[4];
#pragma unroll
                for (int r = 0; r < 4; r++) {
                    int jt = 2 * s + (r >> 1);
                    float x = S[jt][(r & 1) * 2 + 0];
                    float y = S[jt][(r & 1) * 2 + 1];
                    __nv_bfloat16 hx = __float2bfloat16(x);
                    __nv_bfloat16 hy = __float2bfloat16(y);
                    Ah[r] = hpair(hx, hy);
                    Al[r] = hpair(__float2bfloat16(x - __bfloat162float(hx)),
                                  __float2bfloat16(y - __bfloat162float(hy)));
                }
#pragma unroll
                for (int nj = 0; nj < 8; nj++) {
                    uint32_t Bh[2], Bl[2];
                    const __nv_bfloat16* vh = &Vthi[nj * 8 + g][s * 16 + 2 * t];
                    const __nv_bfloat16* vl = &Vtlo[nj * 8 + g][s * 16 + 2 * t];
                    Bh[0] = *(const uint32_t*)vh;
                    Bh[1] = *(const uint32_t*)(vh + 8);
                    Bl[0] = *(const uint32_t*)vl;
                    Bl[1] = *(const uint32_t*)(vl + 8);
                    mma_bf16(O[nj], Ah, Bh);
                    mma_bf16(O[nj], Ah, Bl);
                    mma_bf16(O[nj], Al, Bh);
                }
            }
        }
        __syncthreads();
    }

    float inv0 = 1.f / l0, inv1 = 1.f / l1;
    float* op0 = ctx + ((size_t)(b * CS + qb + g)) * CDIM + h * HD;
    float* op1 = op0 + 8 * (size_t)CDIM;
#pragma unroll
    for (int nj = 0; nj < 8; nj++) {
        int c = nj * 8 + 2 * t;
        op0[c]     = O[nj][0] * inv0;
        op0[c + 1] = O[nj][1] * inv0;
        op1[c]     = O[nj][2] * inv1;
        op1[c + 1] = O[nj][3] * inv1;
    }
}

// ---------------------------------------------------------------
extern "C" void kernel_launch(void* const* d_in, const int* in_sizes, int n_in,
                              void* d_out, int out_size)
{
    const float* x      = (const float*)d_in[0];
    // d_in[1] = causal mask (tril), implemented analytically in flash_attn_mma
    const float* w_kvc  = (const float*)d_in[2];
    const float* b_kvc  = (const float*)d_in[3];
    const float* w_kvu  = (const float*)d_in[4];
    const float* b_kvu  = (const float*)d_in[5];
    const float* w_qc   = (const float*)d_in[6];
    const float* b_qc   = (const float*)d_in[7];
    const float* w_qu   = (const float*)d_in[8];
    const float* b_qu   = (const float*)d_in[9];
    const float* w_o    = (const float*)d_in[10];
    const float* b_o    = (const float*)d_in[11];
    float* out = (float*)d_out;

    float *kvlat, *kvup, *qlat, *Qm, *ctx;
    cudaGetSymbolAddress((void**)&kvlat, g_kvlat);
    cudaGetSymbolAddress((void**)&kvup,  g_kvup);
    cudaGetSymbolAddress((void**)&qlat,  g_qlat);
    cudaGetSymbolAddress((void**)&Qm,    g_q);
    cudaGetSymbolAddress((void**)&ctx,   g_ctx);

    // 1) kv_latent = x @ w_kvc + b_kvc            [8192,128]
    hgemm_bias<<<dim3(LAT/128,    MTOT/128), 256>>>(x,     w_kvc, b_kvc, kvlat, MTOT, LAT,    CDIM);
    // 2) kv_up = kv_latent @ w_kvu + b_kvu        [8192,2048]  (K | V)
    hgemm_bias<<<dim3(2*CDIM/128, MTOT/128), 256>>>(kvlat, w_kvu, b_kvu, kvup,  MTOT, 2*CDIM, LAT);
    // 3) q_lat = x @ w_qc + b_qc                  [8192,256]
    hgemm_bias<<<dim3(QR/128,     MTOT/128), 256>>>(x,     w_qc,  b_qc,  qlat,  MTOT, QR,     CDIM);
    // 4) Q = q_lat @ w_qu + b_qu                  [8192,1024]
    hgemm_bias<<<dim3(CDIM/128,   MTOT/128), 256>>>(qlat,  w_qu,  b_qu,  Qm,    MTOT, CDIM,   QR);
    // 5) causal flash attention (tensor cores) -> ctx
    flash_attn_mma<<<dim3(CS/128, CB*NH), 256>>>(Qm, kvup, ctx);
    // 6) out = ctx @ w_o + b_o                    [8192,1024]
    hgemm_bias<<<dim3(CDIM/128,   MTOT/128), 256>>>(ctx,   w_o,   b_o,   out,   MTOT, CDIM,   CDIM);
}

// round 7
// speedup vs baseline: 4.4062x; 1.2978x over previous
#include <cuda_runtime.h>
#include <cuda_bf16.h>
#include <cstdint>

#define CDIM 1024
#define CS   2048
#define CB   4
#define NH   16
#define HD   64
#define LAT  128
#define QR   256
#define MTOT (CB*CS)   // 8192 tokens

// -------- scratch (static device globals; no runtime allocation) --------
__device__ float g_kvlat[(size_t)MTOT * LAT];            //  4 MB
__device__ float g_qlat [(size_t)MTOT * QR];             //  8 MB
__device__ float g_q    [(size_t)MTOT * CDIM];           // 32 MB
__device__ float g_ctx  [(size_t)MTOT * CDIM];           // 32 MB
__device__ __nv_bfloat16 g_kbf[(size_t)MTOT * CDIM];     // 16 MB  K (bf16)
__device__ __nv_bfloat16 g_vhi[(size_t)MTOT * CDIM];     // 16 MB  V hi
__device__ __nv_bfloat16 g_vlo[(size_t)MTOT * CDIM];     // 16 MB  V lo

// ---------------------------------------------------------------
// common helpers
// ---------------------------------------------------------------
__device__ __forceinline__ void mma_bf16(float d[4], const uint32_t a[4],
                                         const uint32_t b[2])
{
    asm volatile(
        "mma.sync.aligned.m16n8k16.row.col.f32.bf16.bf16.f32 "
        "{%0,%1,%2,%3}, {%4,%5,%6,%7}, {%8,%9}, {%0,%1,%2,%3};\n"
        : "+f"(d[0]), "+f"(d[1]), "+f"(d[2]), "+f"(d[3])
        : "r"(a[0]), "r"(a[1]), "r"(a[2]), "r"(a[3]),
          "r"(b[0]), "r"(b[1]));
}

__device__ __forceinline__ uint32_t pack_bf16(float lo, float hi)
{
    uint32_t r;
    asm("cvt.rn.bf16x2.f32 %0, %2, %1;" : "=r"(r) : "f"(lo), "f"(hi));
    return r;
}

__device__ __forceinline__ uint32_t hpair(__nv_bfloat16 lo, __nv_bfloat16 hi)
{
    __nv_bfloat162 v;
    v.x = lo; v.y = hi;
    return *(uint32_t*)&v;
}

__device__ __forceinline__ void ldsm_x4(uint32_t r[4], const void* p)
{
    uint32_t a = (uint32_t)__cvta_generic_to_shared(p);
    asm volatile("ldmatrix.sync.aligned.m8n8.x4.shared.b16 {%0,%1,%2,%3}, [%4];"
                 : "=r"(r[0]), "=r"(r[1]), "=r"(r[2]), "=r"(r[3]) : "r"(a));
}

__device__ __forceinline__ void ldsm_x4_t(uint32_t r[4], const void* p)
{
    uint32_t a = (uint32_t)__cvta_generic_to_shared(p);
    asm volatile("ldmatrix.sync.aligned.m8n8.x4.trans.shared.b16 {%0,%1,%2,%3}, [%4];"
                 : "=r"(r[0]), "=r"(r[1]), "=r"(r[2]), "=r"(r[3]) : "r"(a));
}

__device__ __forceinline__ void cp_async16(void* s, const void* g)
{
    uint32_t sa = (uint32_t)__cvta_generic_to_shared(s);
    asm volatile("cp.async.cg.shared.global [%0], [%1], 16;" :: "r"(sa), "l"(g));
}

// ---------------------------------------------------------------
// Tensor-core GEMM with bf16 hi/lo 3-pass split (fp32-accurate).
// KVEPI=0: C = A@B + bias (fp32 out).
// KVEPI=1: N==2048; cols [0,1024) -> Kout bf16; cols [1024,2048) -> Vh/Vl bf16 hi/lo.
// ---------------------------------------------------------------
#define APITCH 40
#define BPITCH 136

template<int KVEPI>
__global__ __launch_bounds__(256, 1) void hgemm_bias_t(
    const float* __restrict__ A, const float* __restrict__ B,
    const float* __restrict__ bias, float* __restrict__ C,
    __nv_bfloat16* __restrict__ Kout, __nv_bfloat16* __restrict__ Vh,
    __nv_bfloat16* __restrict__ Vl,
    int M, int N, int K)
{
    __shared__ __align__(16) __nv_bfloat16 Ahs[128 * APITCH];
    __shared__ __align__(16) __nv_bfloat16 Als[128 * APITCH];
    __shared__ __align__(16) __nv_bfloat16 Bhs[32 * BPITCH];
    __shared__ __align__(16) __nv_bfloat16 Bls[32 * BPITCH];

    const int tid  = threadIdx.x;
    const int w    = tid >> 5;
    const int lane = tid & 31;
    const int wm   = w >> 2;
    const int wn   = w & 3;
    const int m0   = wm * 64;
    const int n0   = wn * 32;
    const int row0 = blockIdx.y * 128;
    const int col0 = blockIdx.x * 128;

    float Cacc[4][4][4] = {};
    float4 aR[4], bR[4];

    auto ldTiles = [&](int k0) {
#pragma unroll
        for (int i = 0; i < 4; i++) {
            int f = tid + i * 256;
            int r = f >> 3, c = (f & 7) << 2;
            aR[i] = *(const float4*)(A + (size_t)(row0 + r) * K + k0 + c);
        }
#pragma unroll
        for (int i = 0; i < 4; i++) {
            int f = tid + i * 256;
            int r = f >> 5, c = (f & 31) << 2;
            bR[i] = *(const float4*)(B + (size_t)(k0 + r) * N + col0 + c);
        }
    };

    auto stTiles = [&]() {
#pragma unroll
        for (int i = 0; i < 4; i++) {
            int f = tid + i * 256;
            int r = f >> 3, c = (f & 7) << 2;
            float v[4] = {aR[i].x, aR[i].y, aR[i].z, aR[i].w};
#pragma unroll
            for (int j = 0; j < 2; j++) {
                __nv_bfloat16 h0 = __float2bfloat16(v[2 * j]);
                __nv_bfloat16 h1 = __float2bfloat16(v[2 * j + 1]);
                *(uint32_t*)&Ahs[r * APITCH + c + 2 * j] = hpair(h0, h1);
                *(uint32_t*)&Als[r * APITCH + c + 2 * j] =
                    hpair(__float2bfloat16(v[2 * j]     - __bfloat162float(h0)),
                          __float2bfloat16(v[2 * j + 1] - __bfloat162float(h1)));
            }
        }
#pragma unroll
        for (int i = 0; i < 4; i++) {
            int f = tid + i * 256;
            int r = f >> 5, c = (f & 31) << 2;
            float v[4] = {bR[i].x, bR[i].y, bR[i].z, bR[i].w};
#pragma unroll
            for (int j = 0; j < 2; j++) {
                __nv_bfloat16 h0 = __float2bfloat16(v[2 * j]);
                __nv_bfloat16 h1 = __float2bfloat16(v[2 * j + 1]);
                *(uint32_t*)&Bhs[r * BPITCH + c + 2 * j] = hpair(h0, h1);
                *(uint32_t*)&Bls[r * BPITCH + c + 2 * j] =
                    hpair(__float2bfloat16(v[2 * j]     - __bfloat162float(h0)),
                          __float2bfloat16(v[2 * j + 1] - __bfloat162float(h1)));
            }
        }
    };

    ldTiles(0);
    stTiles();
    __syncthreads();

    const int nk = K >> 5;
    for (int it = 0; it < nk; it++) {
        const int k0 = (it + 1) << 5;
        const bool more = k0 < K;
        if (more) ldTiles(k0);

#pragma unroll
        for (int ks = 0; ks < 2; ks++) {
            uint32_t Af[4][4], Alf[4][4];
#pragma unroll
            for (int mi = 0; mi < 4; mi++) {
                int idx = (m0 + mi * 16 + (lane & 15)) * APITCH
                        + ks * 16 + ((lane >> 4) << 3);
                ldsm_x4(Af[mi],  &Ahs[idx]);
                ldsm_x4(Alf[mi], &Als[idx]);
            }
            uint32_t Bf[4][2], Blf[4][2];
#pragma unroll
            for (int nj = 0; nj < 2; nj++) {
                int rrow = ks * 16 + ((lane >> 3) & 1) * 8 + (lane & 7);
                int ccol = n0 + nj * 16 + ((lane >> 4) << 3);
                uint32_t t4[4];
                ldsm_x4_t(t4, &Bhs[rrow * BPITCH + ccol]);
                Bf[nj * 2][0] = t4[0]; Bf[nj * 2][1] = t4[1];
                Bf[nj * 2 + 1][0] = t4[2]; Bf[nj * 2 + 1][1] = t4[3];
                ldsm_x4_t(t4, &Bls[rrow * BPITCH + ccol]);
                Blf[nj * 2][0] = t4[0]; Blf[nj * 2][1] = t4[1];
                Blf[nj * 2 + 1][0] = t4[2]; Blf[nj * 2 + 1][1] = t4[3];
            }
#pragma unroll
            for (int mi = 0; mi < 4; mi++)
#pragma unroll
                for (int nf = 0; nf < 4; nf++) {
                    mma_bf16(Cacc[mi][nf], Af[mi],  Bf[nf]);
                    mma_bf16(Cacc[mi][nf], Af[mi],  Blf[nf]);
                    mma_bf16(Cacc[mi][nf], Alf[mi], Bf[nf]);
                }
        }
        __syncthreads();
        if (more) {
            stTiles();
            __syncthreads();
        }
    }

    // ---- epilogue ----
    const int g = lane >> 2, t = lane & 3;
#pragma unroll
    for (int mi = 0; mi < 4; mi++) {
#pragma unroll
        for (int nf = 0; nf < 4; nf++) {
            int gr = row0 + m0 + mi * 16 + g;
            int gc = col0 + n0 + nf * 8 + 2 * t;
            float b0 = bias[gc], b1 = bias[gc + 1];
            float v00 = Cacc[mi][nf][0] + b0, v01 = Cacc[mi][nf][1] + b1;
            float v10 = Cacc[mi][nf][2] + b0, v11 = Cacc[mi][nf][3] + b1;
            if (KVEPI == 0) {
                float2 u0 = {v00, v01};
                float2 u1 = {v10, v11};
                *(float2*)&C[(size_t)gr * N + gc] = u0;
                *(float2*)&C[(size_t)(gr + 8) * N + gc] = u1;
            } else {
                if (col0 < 1024) {   // K plane (bf16)
                    *(uint32_t*)&Kout[(size_t)gr * CDIM + gc] =
                        pack_bf16(v00, v01);
                    *(uint32_t*)&Kout[(size_t)(gr + 8) * CDIM + gc] =
                        pack_bf16(v10, v11);
                } else {             // V planes (bf16 hi + lo)
                    int vc = gc - 1024;
                    __nv_bfloat16 h00 = __float2bfloat16(v00);
                    __nv_bfloat16 h01 = __float2bfloat16(v01);
                    __nv_bfloat16 h10 = __float2bfloat16(v10);
                    __nv_bfloat16 h11 = __float2bfloat16(v11);
                    *(uint32_t*)&Vh[(size_t)gr * CDIM + vc] = hpair(h00, h01);
                    *(uint32_t*)&Vh[(size_t)(gr + 8) * CDIM + vc] = hpair(h10, h11);
                    *(uint32_t*)&Vl[(size_t)gr * CDIM + vc] =
                        hpair(__float2bfloat16(v00 - __bfloat162float(h00)),
                              __float2bfloat16(v01 - __bfloat162float(h01)));
                    *(uint32_t*)&Vl[(size_t)(gr + 8) * CDIM + vc] =
                        hpair(__float2bfloat16(v10 - __bfloat162float(h10)),
                              __float2bfloat16(v11 - __bfloat162float(h11)));
                }
            }
        }
    }
}

// ---------------------------------------------------------------
// Causal flash attention v2: pre-split bf16 K/V planes, cp.async
// double-buffered tiles, ldmatrix.trans V fragments (no transpose).
// grid (S/128, B*H), 256 threads. Dynamic smem: 2*3*64*72*2 = 55296 B.
// ---------------------------------------------------------------
#define FPITCH 72
#define TILE_E (64 * FPITCH)

__global__ __launch_bounds__(256) void flash_attn_mma2(
    const float* __restrict__ Qm,
    const __nv_bfloat16* __restrict__ Kbf,
    const __nv_bfloat16* __restrict__ Vhig,
    const __nv_bfloat16* __restrict__ Vlog,
    float* __restrict__ ctx)
{
    extern __shared__ __nv_bfloat16 sm[];

    const int bh = blockIdx.y;
    const int b  = bh >> 4;
    const int h  = bh & 15;
    const int q0 = blockIdx.x * 128;
    const int tid  = threadIdx.x;
    const int w    = tid >> 5;
    const int lane = tid & 31;
    const int g    = lane >> 2;
    const int t    = lane & 3;
    const int qb   = q0 + w * 16;

    // ---- Q fragments (scale folded) ----
    uint32_t Qf[4][4];
    {
        const float* q0p = Qm + ((size_t)(b * CS + qb + g)) * CDIM + h * HD;
        const float* q1p = q0p + 8 * (size_t)CDIM;
        const float sc = 0.125f;
#pragma unroll
        for (int kk = 0; kk < 4; kk++) {
            int c = kk * 16 + 2 * t;
            Qf[kk][0] = pack_bf16(q0p[c]     * sc, q0p[c + 1] * sc);
            Qf[kk][1] = pack_bf16(q1p[c]     * sc, q1p[c + 1] * sc);
            Qf[kk][2] = pack_bf16(q0p[c + 8] * sc, q0p[c + 9] * sc);
            Qf[kk][3] = pack_bf16(q1p[c + 8] * sc, q1p[c + 9] * sc);
        }
    }

    float O[8][4];
#pragma unroll
    for (int i = 0; i < 8; i++)
#pragma unroll
        for (int j = 0; j < 4; j++) O[i][j] = 0.f;
    float m0 = -1e30f, m1 = -1e30f, l0 = 0.f, l1 = 0.f;

    const int nkt = (q0 + 128) / 64;

    auto loadTile = [&](int kt, int buf) {
        __nv_bfloat16* bs = sm + buf * 3 * TILE_E;
        const size_t rowbase = ((size_t)(b * CS + kt * 64)) * CDIM + h * HD;
#pragma unroll
        for (int i = 0; i < 6; i++) {
            int id = tid + i * 256;        // 0..1535
            int plane = id >> 9;
            int rem = id & 511;
            int r = rem >> 3;
            int c = (rem & 7) << 3;
            const __nv_bfloat16* gp =
                (plane == 0 ? Kbf : plane == 1 ? Vhig : Vlog)
                + rowbase + (size_t)r * CDIM + c;
            cp_async16(bs + plane * TILE_E + r * FPITCH + c, gp);
        }
        asm volatile("cp.async.commit_group;" ::: "memory");
    };

    loadTile(0, 0);

    for (int kt = 0; kt < nkt; kt++) {
        const int buf = kt & 1;
        if (kt + 1 < nkt) {
            loadTile(kt + 1, buf ^ 1);
            asm volatile("cp.async.wait_group 1;" ::: "memory");
        } else {
            asm volatile("cp.async.wait_group 0;" ::: "memory");
        }
        __syncthreads();

        if (kt * 64 <= qb + 15) {
            const __nv_bfloat16* Ks = sm + buf * 3 * TILE_E;
            const __nv_bfloat16* Vh = Ks + TILE_E;
            const __nv_bfloat16* Vl = Ks + 2 * TILE_E;

            // ---- S = Q K^T ----
            float S[8][4];
#pragma unroll
            for (int j = 0; j < 8; j++) {
                S[j][0] = S[j][1] = S[j][2] = S[j][3] = 0.f;
#pragma unroll
                for (int kk = 0; kk < 4; kk++) {
                    uint32_t Bk[2];
                    const __nv_bfloat16* kr = &Ks[(j * 8 + g) * FPITCH + kk * 16 + 2 * t];
                    Bk[0] = *(const uint32_t*)kr;
                    Bk[1] = *(const uint32_t*)(kr + 8);
                    mma_bf16(S[j], Qf[kk], Bk);
                }
            }
            // ---- causal mask ----
            if (kt * 64 + 63 > qb) {
#pragma unroll
                for (int j = 0; j < 8; j++) {
                    int key = kt * 64 + j * 8 + 2 * t;
                    if (key     > qb + g)     S[j][0] = -1e30f;
                    if (key + 1 > qb + g)     S[j][1] = -1e30f;
                    if (key     > qb + g + 8) S[j][2] = -1e30f;
                    if (key + 1 > qb + g + 8) S[j][3] = -1e30f;
                }
            }
            // ---- online softmax ----
            float rmax0 = -1e30f, rmax1 = -1e30f;
#pragma unroll
            for (int j = 0; j < 8; j++) {
                rmax0 = fmaxf(rmax0, fmaxf(S[j][0], S[j][1]));
                rmax1 = fmaxf(rmax1, fmaxf(S[j][2], S[j][3]));
            }
#pragma unroll
            for (int off = 1; off <= 2; off <<= 1) {
                rmax0 = fmaxf(rmax0, __shfl_xor_sync(0xffffffffu, rmax0, off));
                rmax1 = fmaxf(rmax1, __shfl_xor_sync(0xffffffffu, rmax1, off));
            }
            float mn0 = fmaxf(m0, rmax0), mn1 = fmaxf(m1, rmax1);
            float sc0 = __expf(m0 - mn0), sc1 = __expf(m1 - mn1);
            float ls0 = 0.f, ls1 = 0.f;
#pragma unroll
            for (int j = 0; j < 8; j++) {
                S[j][0] = __expf(S[j][0] - mn0); ls0 += S[j][0];
                S[j][1] = __expf(S[j][1] - mn0); ls0 += S[j][1];
                S[j][2] = __expf(S[j][2] - mn1); ls1 += S[j][2];
                S[j][3] = __expf(S[j][3] - mn1); ls1 += S[j][3];
            }
#pragma unroll
            for (int off = 1; off <= 2; off <<= 1) {
                ls0 += __shfl_xor_sync(0xffffffffu, ls0, off);
                ls1 += __shfl_xor_sync(0xffffffffu, ls1, off);
            }
            l0 = l0 * sc0 + ls0;
            l1 = l1 * sc1 + ls1;
            m0 = mn0; m1 = mn1;
#pragma unroll
            for (int nj = 0; nj < 8; nj++) {
                O[nj][0] *= sc0; O[nj][1] *= sc0;
                O[nj][2] *= sc1; O[nj][3] *= sc1;
            }
            // ---- O += P V  (P hi/lo via cvt; V fragments via ldmatrix.trans) ----
#pragma unroll
            for (int s = 0; s < 4; s++) {
                uint32_t Ah[4], Al[4];
#pragma unroll
                for (int r = 0; r < 4; r++) {
                    int jt = 2 * s + (r >> 1);
                    float x = S[jt][(r & 1) * 2 + 0];
                    float y = S[jt][(r & 1) * 2 + 1];
                    __nv_bfloat16 hx = __float2bfloat16(x);
                    __nv_bfloat16 hy = __float2bfloat16(y);
                    Ah[r] = hpair(hx, hy);
                    Al[r] = hpair(__float2bfloat16(x - __bfloat162float(hx)),
                                  __float2bfloat16(y - __bfloat162float(hy)));
                }
                const int rrow = s * 16 + ((lane >> 3) & 1) * 8 + (lane & 7);
#pragma unroll
                for (int nt = 0; nt < 4; nt++) {
                    const int ccol = nt * 16 + ((lane >> 4) << 3);
                    uint32_t th[4], tl[4];
                    ldsm_x4_t(th, &Vh[rrow * FPITCH + ccol]);
                    ldsm_x4_t(tl, &Vl[rrow * FPITCH + ccol]);
                    uint32_t Bh0[2] = {th[0], th[1]}, Bh1[2] = {th[2], th[3]};
                    uint32_t Bl0[2] = {tl[0], tl[1]}, Bl1[2] = {tl[2], tl[3]};
                    mma_bf16(O[nt * 2],     Ah, Bh0);
                    mma_bf16(O[nt * 2],     Ah, Bl0);
                    mma_bf16(O[nt * 2],     Al, Bh0);
                    mma_bf16(O[nt * 2 + 1], Ah, Bh1);
                    mma_bf16(O[nt * 2 + 1], Ah, Bl1);
                    mma_bf16(O[nt * 2 + 1], Al, Bh1);
                }
            }
        }
        __syncthreads();
    }

    // ---- epilogue ----
    float inv0 = 1.f / l0, inv1 = 1.f / l1;
    float* op0 = ctx + ((size_t)(b * CS + qb + g)) * CDIM + h * HD;
    float* op1 = op0 + 8 * (size_t)CDIM;
#pragma unroll
    for (int nj = 0; nj < 8; nj++) {
        int c = nj * 8 + 2 * t;
        op0[c]     = O[nj][0] * inv0;
        op0[c + 1] = O[nj][1] * inv0;
        op1[c]     = O[nj][2] * inv1;
        op1[c + 1] = O[nj][3] * inv1;
    }
}

// ---------------------------------------------------------------
extern "C" void kernel_launch(void* const* d_in, const int* in_sizes, int n_in,
                              void* d_out, int out_size)
{
    const float* x      = (const float*)d_in[0];
    // d_in[1] = causal mask (tril), implemented analytically in flash_attn_mma2
    const float* w_kvc  = (const float*)d_in[2];
    const float* b_kvc  = (const float*)d_in[3];
    const float* w_kvu  = (const float*)d_in[4];
    const float* b_kvu  = (const float*)d_in[5];
    const float* w_qc   = (const float*)d_in[6];
    const float* b_qc   = (const float*)d_in[7];
    const float* w_qu   = (const float*)d_in[8];
    const float* b_qu   = (const float*)d_in[9];
    const float* w_o    = (const float*)d_in[10];
    const float* b_o    = (const float*)d_in[11];
    float* out = (float*)d_out;

    float *kvlat, *qlat, *Qm, *ctx;
    __nv_bfloat16 *kbf, *vhi, *vlo;
    cudaGetSymbolAddress((void**)&kvlat, g_kvlat);
    cudaGetSymbolAddress((void**)&qlat,  g_qlat);
    cudaGetSymbolAddress((void**)&Qm,    g_q);
    cudaGetSymbolAddress((void**)&ctx,   g_ctx);
    cudaGetSymbolAddress((void**)&kbf,   g_kbf);
    cudaGetSymbolAddress((void**)&vhi,   g_vhi);
    cudaGetSymbolAddress((void**)&vlo,   g_vlo);

    static bool attr_set = false;
    if (!attr_set) {
        cudaFuncSetAttribute(flash_attn_mma2,
                             cudaFuncAttributeMaxDynamicSharedMemorySize,
                             2 * 3 * TILE_E * (int)sizeof(__nv_bfloat16));
        attr_set = true;
    }

    // 1) kv_latent = x @ w_kvc + b_kvc            [8192,128]
    hgemm_bias_t<0><<<dim3(LAT/128,    MTOT/128), 256>>>(x,     w_kvc, b_kvc, kvlat,
                                                         nullptr, nullptr, nullptr,
                                                         MTOT, LAT,    CDIM);
    // 2) K/V = split(kv_latent @ w_kvu + b_kvu)   -> bf16 planes
    hgemm_bias_t<1><<<dim3(2*CDIM/128, MTOT/128), 256>>>(kvlat, w_kvu, b_kvu, nullptr,
                                                         kbf, vhi, vlo,
                                                         MTOT, 2*CDIM, LAT);
    // 3) q_lat = x @ w_qc + b_qc                  [8192,256]
    hgemm_bias_t<0><<<dim3(QR/128,     MTOT/128), 256>>>(x,     w_qc,  b_qc,  qlat,
                                                         nullptr, nullptr, nullptr,
                                                         MTOT, QR,     CDIM);
    // 4) Q = q_lat @ w_qu + b_qu                  [8192,1024]
    hgemm_bias_t<0><<<dim3(CDIM/128,   MTOT/128), 256>>>(qlat,  w_qu,  b_qu,  Qm,
                                                         nullptr, nullptr, nullptr,
                                                         MTOT, CDIM,   QR);
    // 5) causal flash attention (tensor cores) -> ctx
    flash_attn_mma2<<<dim3(CS/128, CB*NH), 256,
                      2 * 3 * TILE_E * (int)sizeof(__nv_bfloat16)>>>(Qm, kbf, vhi, vlo, ctx);
    // 6) out = ctx @ w_o + b_o                    [8192,1024]
    hgemm_bias_t<0><<<dim3(CDIM/128,   MTOT/128), 256>>>(ctx,   w_o,   b_o,   out,
                                                         nullptr, nullptr, nullptr,
                                                         MTOT, CDIM,   CDIM);
}

// round 10
// speedup vs baseline: 4.9928x; 1.1331x over previous
#include <cuda_runtime.h>
#include <cuda_bf16.h>
#include <cuda_fp16.h>
#include <cstdint>

#define CDIM 1024
#define CS   2048
#define CB   4
#define NH   16
#define HD   64
#define LAT  128
#define QR   256
#define MTOT (CB*CS)   // 8192 tokens

// -------- scratch (static device globals; no runtime allocation) --------
__device__ float g_kvlat[(size_t)MTOT * LAT];        //  4 MB
__device__ float g_qlat [(size_t)MTOT * QR];         //  8 MB
__device__ float g_q    [(size_t)MTOT * CDIM];       // 32 MB
__device__ float g_ctx  [(size_t)MTOT * CDIM];       // 32 MB
__device__ __half g_kf16[(size_t)MTOT * CDIM];       // 16 MB  K (fp16)
__device__ __half g_vhi [(size_t)MTOT * CDIM];       // 16 MB  V hi (fp16)
__device__ __half g_vlo [(size_t)MTOT * CDIM];       // 16 MB  V lo (fp16)

// ---------------------------------------------------------------
// common helpers
// ---------------------------------------------------------------
__device__ __forceinline__ void mma_bf16(float d[4], const uint32_t a[4],
                                         const uint32_t b[2])
{
    asm volatile(
        "mma.sync.aligned.m16n8k16.row.col.f32.bf16.bf16.f32 "
        "{%0,%1,%2,%3}, {%4,%5,%6,%7}, {%8,%9}, {%0,%1,%2,%3};\n"
        : "+f"(d[0]), "+f"(d[1]), "+f"(d[2]), "+f"(d[3])
        : "r"(a[0]), "r"(a[1]), "r"(a[2]), "r"(a[3]),
          "r"(b[0]), "r"(b[1]));
}

__device__ __forceinline__ void mma_f16(float d[4], const uint32_t a[4],
                                        const uint32_t b[2])
{
    asm volatile(
        "mma.sync.aligned.m16n8k16.row.col.f32.f16.f16.f32 "
        "{%0,%1,%2,%3}, {%4,%5,%6,%7}, {%8,%9}, {%0,%1,%2,%3};\n"
        : "+f"(d[0]), "+f"(d[1]), "+f"(d[2]), "+f"(d[3])
        : "r"(a[0]), "r"(a[1]), "r"(a[2]), "r"(a[3]),
          "r"(b[0]), "r"(b[1]));
}

__device__ __forceinline__ uint32_t pack_bf16(float lo, float hi)
{
    uint32_t r;
    asm("cvt.rn.bf16x2.f32 %0, %2, %1;" : "=r"(r) : "f"(lo), "f"(hi));
    return r;
}

__device__ __forceinline__ uint32_t pack_f16(float lo, float hi)
{
    uint32_t r;
    asm("cvt.rn.f16x2.f32 %0, %2, %1;" : "=r"(r) : "f"(lo), "f"(hi));
    return r;
}

__device__ __forceinline__ uint32_t hpair(__nv_bfloat16 lo, __nv_bfloat16 hi)
{
    __nv_bfloat162 v;
    v.x = lo; v.y = hi;
    return *(uint32_t*)&v;
}

__device__ __forceinline__ uint32_t hpair16(__half lo, __half hi)
{
    __half2 v;
    v.x = lo; v.y = hi;
    return *(uint32_t*)&v;
}

__device__ __forceinline__ void ldsm_x4(uint32_t r[4], const void* p)
{
    uint32_t a = (uint32_t)__cvta_generic_to_shared(p);
    asm volatile("ldmatrix.sync.aligned.m8n8.x4.shared.b16 {%0,%1,%2,%3}, [%4];"
                 : "=r"(r[0]), "=r"(r[1]), "=r"(r[2]), "=r"(r[3]) : "r"(a));
}

__device__ __forceinline__ void ldsm_x4_t(uint32_t r[4], const void* p)
{
    uint32_t a = (uint32_t)__cvta_generic_to_shared(p);
    asm volatile("ldmatrix.sync.aligned.m8n8.x4.trans.shared.b16 {%0,%1,%2,%3}, [%4];"
                 : "=r"(r[0]), "=r"(r[1]), "=r"(r[2]), "=r"(r[3]) : "r"(a));
}

__device__ __forceinline__ void cp_async16(void* s, const void* g)
{
    uint32_t sa = (uint32_t)__cvta_generic_to_shared(s);
    asm volatile("cp.async.cg.shared.global [%0], [%1], 16;" :: "r"(sa), "l"(g));
}

// ---------------------------------------------------------------
// Tensor-core GEMM with bf16 hi/lo 3-pass split (fp32-accurate).
// MODE 0: C = A@B + bias (fp32).
// MODE 1: N==2048; cols [0,1024) -> g_kf16 (fp16); cols [1024,2048) -> Vh/Vl fp16 hi/lo.
//         P1=Kout, P2=Vh, P3=Vl.
// MODE 2: fused dual-output projection. Block cols [0,128) -> C (=kvlat, bias, B);
//         block cols [128,384) -> P3 (=qlat) using B2=P1, bias2=P2. grid.x = 3.
// ---------------------------------------------------------------
#define APITCH 40
#define BPITCH 136

template<int MODE>
__global__ __launch_bounds__(256, 1) void hgemm_bias_t(
    const float* __restrict__ A, const float* __restrict__ B,
    const float* __restrict__ bias, float* __restrict__ C,
    void* __restrict__ P1, void* __restrict__ P2, void* __restrict__ P3,
    int M, int N, int K)
{
    __shared__ __align__(16) __nv_bfloat16 Ahs[128 * APITCH];
    __shared__ __align__(16) __nv_bfloat16 Als[128 * APITCH];
    __shared__ __align__(16) __nv_bfloat16 Bhs[32 * BPITCH];
    __shared__ __align__(16) __nv_bfloat16 Bls[32 * BPITCH];

    const int tid  = threadIdx.x;
    const int w    = tid >> 5;
    const int lane = tid & 31;
    const int wm   = w >> 2;
    const int wn   = w & 3;
    const int m0   = wm * 64;
    const int n0   = wn * 32;
    const int row0 = blockIdx.y * 128;
    const int col0 = blockIdx.x * 128;

    // per-block operand selection (MODE 2 fuses two projections)
    const float* Bp   = B;
    const float* bip  = bias;
    float*       Cp   = C;
    int Nl = N, cl = col0;
    if (MODE == 2) {
        if (col0 < LAT) { Nl = LAT; cl = col0; }
        else {
            Bp  = (const float*)P1;
            bip = (const float*)P2;
            Cp  = (float*)P3;
            Nl  = QR;
            cl  = col0 - LAT;
        }
    }

    float Cacc[4][4][4] = {};
    float4 aR[4], bR[4];

    auto ldTiles = [&](int k0) {
#pragma unroll
        for (int i = 0; i < 4; i++) {
            int f = tid + i * 256;
            int r = f >> 3, c = (f & 7) << 2;
            aR[i] = *(const float4*)(A + (size_t)(row0 + r) * K + k0 + c);
        }
#pragma unroll
        for (int i = 0; i < 4; i++) {
            int f = tid + i * 256;
            int r = f >> 5, c = (f & 31) << 2;
            bR[i] = *(const float4*)(Bp + (size_t)(k0 + r) * Nl + cl + c);
        }
    };

    auto stTiles = [&]() {
#pragma unroll
        for (int i = 0; i < 4; i++) {
            int f = tid + i * 256;
            int r = f >> 3, c = (f & 7) << 2;
            float v[4] = {aR[i].x, aR[i].y, aR[i].z, aR[i].w};
#pragma unroll
            for (int j = 0; j < 2; j++) {
                __nv_bfloat16 h0 = __float2bfloat16(v[2 * j]);
                __nv_bfloat16 h1 = __float2bfloat16(v[2 * j + 1]);
                *(uint32_t*)&Ahs[r * APITCH + c + 2 * j] = hpair(h0, h1);
                *(uint32_t*)&Als[r * APITCH + c + 2 * j] =
                    hpair(__float2bfloat16(v[2 * j]     - __bfloat162float(h0)),
                          __float2bfloat16(v[2 * j + 1] - __bfloat162float(h1)));
            }
        }
#pragma unroll
        for (int i = 0; i < 4; i++) {
            int f = tid + i * 256;
            int r = f >> 5, c = (f & 31) << 2;
            float v[4] = {bR[i].x, bR[i].y, bR[i].z, bR[i].w};
#pragma unroll
            for (int j = 0; j < 2; j++) {
                __nv_bfloat16 h0 = __float2bfloat16(v[2 * j]);
                __nv_bfloat16 h1 = __float2bfloat16(v[2 * j + 1]);
                *(uint32_t*)&Bhs[r * BPITCH + c + 2 * j] = hpair(h0, h1);
                *(uint32_t*)&Bls[r * BPITCH + c + 2 * j] =
                    hpair(__float2bfloat16(v[2 * j]     - __bfloat162float(h0)),
                          __float2bfloat16(v[2 * j + 1] - __bfloat162float(h1)));
            }
        }
    };

    ldTiles(0);
    stTiles();
    __syncthreads();

    const int nk = K >> 5;
    for (int it = 0; it < nk; it++) {
        const int k0 = (it + 1) << 5;
        const bool more = k0 < K;
        if (more) ldTiles(k0);

#pragma unroll
        for (int ks = 0; ks < 2; ks++) {
            uint32_t Af[4][4], Alf[4][4];
#pragma unroll
            for (int mi = 0; mi < 4; mi++) {
                int idx = (m0 + mi * 16 + (lane & 15)) * APITCH
                        + ks * 16 + ((lane >> 4) << 3);
                ldsm_x4(Af[mi],  &Ahs[idx]);
                ldsm_x4(Alf[mi], &Als[idx]);
            }
            uint32_t Bf[4][2], Blf[4][2];
#pragma unroll
            for (int nj = 0; nj < 2; nj++) {
                int rrow = ks * 16 + ((lane >> 3) & 1) * 8 + (lane & 7);
                int ccol = n0 + nj * 16 + ((lane >> 4) << 3);
                uint32_t t4[4];
                ldsm_x4_t(t4, &Bhs[rrow * BPITCH + ccol]);
                Bf[nj * 2][0] = t4[0]; Bf[nj * 2][1] = t4[1];
                Bf[nj * 2 + 1][0] = t4[2]; Bf[nj * 2 + 1][1] = t4[3];
                ldsm_x4_t(t4, &Bls[rrow * BPITCH + ccol]);
                Blf[nj * 2][0] = t4[0]; Blf[nj * 2][1] = t4[1];
                Blf[nj * 2 + 1][0] = t4[2]; Blf[nj * 2 + 1][1] = t4[3];
            }
#pragma unroll
            for (int mi = 0; mi < 4; mi++)
#pragma unroll
                for (int nf = 0; nf < 4; nf++) {
                    mma_bf16(Cacc[mi][nf], Af[mi],  Bf[nf]);
                    mma_bf16(Cacc[mi][nf], Af[mi],  Blf[nf]);
                    mma_bf16(Cacc[mi][nf], Alf[mi], Bf[nf]);
                }
        }
        __syncthreads();
        if (more) {
            stTiles();
            __syncthreads();
        }
    }

    // ---- epilogue ----
    const int g = lane >> 2, t = lane & 3;
#pragma unroll
    for (int mi = 0; mi < 4; mi++) {
#pragma unroll
        for (int nf = 0; nf < 4; nf++) {
            int gr = row0 + m0 + mi * 16 + g;
            int gc = cl + n0 + nf * 8 + 2 * t;
            float b0 = bip[gc], b1 = bip[gc + 1];
            float v00 = Cacc[mi][nf][0] + b0, v01 = Cacc[mi][nf][1] + b1;
            float v10 = Cacc[mi][nf][2] + b0, v11 = Cacc[mi][nf][3] + b1;
            if (MODE != 1) {
                float2 u0 = {v00, v01};
                float2 u1 = {v10, v11};
                *(float2*)&Cp[(size_t)gr * Nl + gc] = u0;
                *(float2*)&Cp[(size_t)(gr + 8) * Nl + gc] = u1;
            } else {
                __half* Kout = (__half*)P1;
                __half* Vh   = (__half*)P2;
                __half* Vl   = (__half*)P3;
                if (col0 < 1024) {   // K plane (fp16)
                    *(uint32_t*)&Kout[(size_t)gr * CDIM + gc] = pack_f16(v00, v01);
                    *(uint32_t*)&Kout[(size_t)(gr + 8) * CDIM + gc] = pack_f16(v10, v11);
                } else {             // V planes (fp16 hi + lo)
                    int vc = gc - 1024;
                    __half h00 = __float2half(v00);
                    __half h01 = __float2half(v01);
                    __half h10 = __float2half(v10);
                    __half h11 = __float2half(v11);
                    *(uint32_t*)&Vh[(size_t)gr * CDIM + vc] = hpair16(h00, h01);
                    *(uint32_t*)&Vh[(size_t)(gr + 8) * CDIM + vc] = hpair16(h10, h11);
                    *(uint32_t*)&Vl[(size_t)gr * CDIM + vc] =
                        hpair16(__float2half(v00 - __half2float(h00)),
                                __float2half(v01 - __half2float(h01)));
                    *(uint32_t*)&Vl[(size_t)(gr + 8) * CDIM + vc] =
                        hpair16(__float2half(v10 - __half2float(h10)),
                                __float2half(v11 - __half2float(h11)));
                }
            }
        }
    }
}

// ---------------------------------------------------------------
// Causal flash attention v3 (fp16): pre-split fp16 K / V-hi / V-lo planes,
// cp.async double-buffered tiles, ldmatrix for both QK and PV fragments,
// exp2-domain softmax, longest-CTA-first scheduling.
// grid (S/128, B*H), 256 threads. Dynamic smem 2*3*64*72*2 = 55296 B.
// ---------------------------------------------------------------
#define FPITCH 72
#define TILE_E (64 * FPITCH)

__global__ __launch_bounds__(256) void flash_attn_mma3(
    const float* __restrict__ Qm,
    const __half* __restrict__ Kfg,
    const __half* __restrict__ Vhig,
    const __half* __restrict__ Vlog,
    float* __restrict__ ctx)
{
    extern __shared__ __half sm[];

    const int bh = blockIdx.y;
    const int b  = bh >> 4;
    const int h  = bh & 15;
    const int q0 = (gridDim.x - 1 - blockIdx.x) * 128;  // longest first
    const int tid  = threadIdx.x;
    const int w    = tid >> 5;
    const int lane = tid & 31;
    const int g    = lane >> 2;
    const int t    = lane & 3;
    const int qb   = q0 + w * 16;

    // ---- Q fragments fp16 (scale * log2e folded) ----
    uint32_t Qf[4][4];
    {
        const float* q0p = Qm + ((size_t)(b * CS + qb + g)) * CDIM + h * HD;
        const float* q1p = q0p + 8 * (size_t)CDIM;
        const float sc = 0.125f * 1.4426950408889634f;
#pragma unroll
        for (int kk = 0; kk < 4; kk++) {
            int c = kk * 16 + 2 * t;
            Qf[kk][0] = pack_f16(q0p[c]     * sc, q0p[c + 1] * sc);
            Qf[kk][1] = pack_f16(q1p[c]     * sc, q1p[c + 1] * sc);
            Qf[kk][2] = pack_f16(q0p[c + 8] * sc, q0p[c + 9] * sc);
            Qf[kk][3] = pack_f16(q1p[c + 8] * sc, q1p[c + 9] * sc);
        }
    }

    float O[8][4];
#pragma unroll
    for (int i = 0; i < 8; i++)
#pragma unroll
        for (int j = 0; j < 4; j++) O[i][j] = 0.f;
    float m0 = -1e30f, m1 = -1e30f, l0 = 0.f, l1 = 0.f;

    const int nkt = (q0 + 128) / 64;

    auto loadTile = [&](int kt, int buf) {
        __half* bs = sm + buf * 3 * TILE_E;
        const size_t rowbase = ((size_t)(b * CS + kt * 64)) * CDIM + h * HD;
#pragma unroll
        for (int i = 0; i < 6; i++) {
            int id = tid + i * 256;        // 0..1535
            int plane = id >> 9;
            int rem = id & 511;
            int r = rem >> 3;
            int c = (rem & 7) << 3;
            const __half* gp =
                (plane == 0 ? Kfg : plane == 1 ? Vhig : Vlog)
                + rowbase + (size_t)r * CDIM + c;
            cp_async16(bs + plane * TILE_E + r * FPITCH + c, gp);
        }
        asm volatile("cp.async.commit_group;" ::: "memory");
    };

    loadTile(0, 0);

    for (int kt = 0; kt < nkt; kt++) {
        const int buf = kt & 1;
        if (kt + 1 < nkt) {
            loadTile(kt + 1, buf ^ 1);
            asm volatile("cp.async.wait_group 1;" ::: "memory");
        } else {
            asm volatile("cp.async.wait_group 0;" ::: "memory");
        }
        __syncthreads();

        if (kt * 64 <= qb + 15) {
            const __half* Ks = sm + buf * 3 * TILE_E;
            const __half* Vh = Ks + TILE_E;
            const __half* Vl = Ks + 2 * TILE_E;

            // ---- S = Q K^T  (K fragments via ldmatrix, rows = keys) ----
            float S[8][4];
#pragma unroll
            for (int j = 0; j < 8; j++) {
                S[j][0] = S[j][1] = S[j][2] = S[j][3] = 0.f;
#pragma unroll
                for (int kkp = 0; kkp < 2; kkp++) {
                    uint32_t t4[4];
                    const __half* kr = &Ks[(j * 8 + (lane & 7)) * FPITCH
                                           + kkp * 32 + ((lane >> 3) << 3)];
                    ldsm_x4(t4, kr);
                    uint32_t b0[2] = {t4[0], t4[1]};
                    uint32_t b1[2] = {t4[2], t4[3]};
                    mma_f16(S[j], Qf[2 * kkp],     b0);
                    mma_f16(S[j], Qf[2 * kkp + 1], b1);
                }
            }
            // ---- causal mask ----
            if (kt * 64 + 63 > qb) {
#pragma unroll
                for (int j = 0; j < 8; j++) {
                    int key = kt * 64 + j * 8 + 2 * t;
                    if (key     > qb + g)     S[j][0] = -1e30f;
                    if (key + 1 > qb + g)     S[j][1] = -1e30f;
                    if (key     > qb + g + 8) S[j][2] = -1e30f;
                    if (key + 1 > qb + g + 8) S[j][3] = -1e30f;
                }
            }
            // ---- online softmax (base-2 domain) ----
            float rmax0 = -1e30f, rmax1 = -1e30f;
#pragma unroll
            for (int j = 0; j < 8; j++) {
                rmax0 = fmaxf(rmax0, fmaxf(S[j][0], S[j][1]));
                rmax1 = fmaxf(rmax1, fmaxf(S[j][2], S[j][3]));
            }
#pragma unroll
            for (int off = 1; off <= 2; off <<= 1) {
                rmax0 = fmaxf(rmax0, __shfl_xor_sync(0xffffffffu, rmax0, off));
                rmax1 = fmaxf(rmax1, __shfl_xor_sync(0xffffffffu, rmax1, off));
            }
            float mn0 = fmaxf(m0, rmax0), mn1 = fmaxf(m1, rmax1);
            float sc0 = exp2f(m0 - mn0), sc1 = exp2f(m1 - mn1);
            float ls0 = 0.f, ls1 = 0.f;
#pragma unroll
            for (int j = 0; j < 8; j++) {
                S[j][0] = exp2f(S[j][0] - mn0); ls0 += S[j][0];
                S[j][1] = exp2f(S[j][1] - mn0); ls0 += S[j][1];
                S[j][2] = exp2f(S[j][2] - mn1); ls1 += S[j][2];
                S[j][3] = exp2f(S[j][3] - mn1); ls1 += S[j][3];
            }
#pragma unroll
            for (int off = 1; off <= 2; off <<= 1) {
                ls0 += __shfl_xor_sync(0xffffffffu, ls0, off);
                ls1 += __shfl_xor_sync(0xffffffffu, ls1, off);
            }
            l0 = l0 * sc0 + ls0;
            l1 = l1 * sc1 + ls1;
            m0 = mn0; m1 = mn1;
#pragma unroll
            for (int nj = 0; nj < 8; nj++) {
                O[nj][0] *= sc0; O[nj][1] *= sc0;
                O[nj][2] *= sc1; O[nj][3] *= sc1;
            }
            // ---- O += P V  (P fp16 single; V fp16 hi/lo, 2 passes) ----
#pragma unroll
            for (int s = 0; s < 4; s++) {
                uint32_t Ah[4];
#pragma unroll
                for (int r = 0; r < 4; r++) {
                    int jt = 2 * s + (r >> 1);
                    Ah[r] = pack_f16(S[jt][(r & 1) * 2 + 0],
                                     S[jt][(r & 1) * 2 + 1]);
                }
                const int rrow = s * 16 + ((lane >> 3) & 1) * 8 + (lane & 7);
#pragma unroll
                for (int nt = 0; nt < 4; nt++) {
                    const int ccol = nt * 16 + ((lane >> 4) << 3);
                    uint32_t th[4], tl[4];
                    ldsm_x4_t(th, &Vh[rrow * FPITCH + ccol]);
                    ldsm_x4_t(tl, &Vl[rrow * FPITCH + ccol]);
                    uint32_t Bh0[2] = {th[0], th[1]}, Bh1[2] = {th[2], th[3]};
                    uint32_t Bl0[2] = {tl[0], tl[1]}, Bl1[2] = {tl[2], tl[3]};
                    mma_f16(O[nt * 2],     Ah, Bh0);
                    mma_f16(O[nt * 2],     Ah, Bl0);
                    mma_f16(O[nt * 2 + 1], Ah, Bh1);
                    mma_f16(O[nt * 2 + 1], Ah, Bl1);
                }
            }
        }
        __syncthreads();
    }

    // ---- epilogue ----
    float inv0 = 1.f / l0, inv1 = 1.f / l1;
    float* op0 = ctx + ((size_t)(b * CS + qb + g)) * CDIM + h * HD;
    float* op1 = op0 + 8 * (size_t)CDIM;
#pragma unroll
    for (int nj = 0; nj < 8; nj++) {
        int c = nj * 8 + 2 * t;
        op0[c]     = O[nj][0] * inv0;
        op0[c + 1] = O[nj][1] * inv0;
        op1[c]     = O[nj][2] * inv1;
        op1[c + 1] = O[nj][3] * inv1;
    }
}

// ---------------------------------------------------------------
extern "C" void kernel_launch(void* const* d_in, const int* in_sizes, int n_in,
                              void* d_out, int out_size)
{
    const float* x      = (const float*)d_in[0];
    // d_in[1] = causal mask (tril), implemented analytically in flash_attn_mma3
    const float* w_kvc  = (const float*)d_in[2];
    const float* b_kvc  = (const float*)d_in[3];
    const float* w_kvu  = (const float*)d_in[4];
    const float* b_kvu  = (const float*)d_in[5];
    const float* w_qc   = (const float*)d_in[6];
    const float* b_qc   = (const float*)d_in[7];
    const float* w_qu   = (const float*)d_in[8];
    const float* b_qu   = (const float*)d_in[9];
    const float* w_o    = (const float*)d_in[10];
    const float* b_o    = (const float*)d_in[11];
    float* out = (float*)d_out;

    float *kvlat, *qlat, *Qm, *ctx;
    __half *kf, *vhi, *vlo;
    cudaGetSymbolAddress((void**)&kvlat, g_kvlat);
    cudaGetSymbolAddress((void**)&qlat,  g_qlat);
    cudaGetSymbolAddress((void**)&Qm,    g_q);
    cudaGetSymbolAddress((void**)&ctx,   g_ctx);
    cudaGetSymbolAddress((void**)&kf,    g_kf16);
    cudaGetSymbolAddress((void**)&vhi,   g_vhi);
    cudaGetSymbolAddress((void**)&vlo,   g_vlo);

    static bool attr_set = false;
    if (!attr_set) {
        cudaFuncSetAttribute(flash_attn_mma3,
                             cudaFuncAttributeMaxDynamicSharedMemorySize,
                             2 * 3 * TILE_E * (int)sizeof(__half));
        attr_set = true;
    }

    // 1+3) fused: kv_latent = x@w_kvc + b_kvc  AND  q_lat = x@w_qc + b_qc
    hgemm_bias_t<2><<<dim3((LAT+QR)/128, MTOT/128), 256>>>(
        x, w_kvc, b_kvc, kvlat,
        (void*)w_qc, (void*)b_qc, (void*)qlat,
        MTOT, LAT, CDIM);
    // 2) K/V = split(kv_latent @ w_kvu + b_kvu)  -> fp16 planes
    hgemm_bias_t<1><<<dim3(2*CDIM/128, MTOT/128), 256>>>(
        kvlat, w_kvu, b_kvu, nullptr,
        (void*)kf, (void*)vhi, (void*)vlo,
        MTOT, 2*CDIM, LAT);
    // 4) Q = q_lat @ w_qu + b_qu                [8192,1024]
    hgemm_bias_t<0><<<dim3(CDIM/128, MTOT/128), 256>>>(
        qlat, w_qu, b_qu, Qm,
        nullptr, nullptr, nullptr,
        MTOT, CDIM, QR);
    // 5) causal flash attention (fp16 tensor cores) -> ctx
    flash_attn_mma3<<<dim3(CS/128, CB*NH), 256,
                      2 * 3 * TILE_E * (int)sizeof(__half)>>>(Qm, kf, vhi, vlo, ctx);
    // 6) out = ctx @ w_o + b_o                  [8192,1024]
    hgemm_bias_t<0><<<dim3(CDIM/128, MTOT/128), 256>>>(
        ctx, w_o, b_o, out,
        nullptr, nullptr, nullptr,
        MTOT, CDIM, CDIM);
}

// round 12
// speedup vs baseline: 5.6056x; 1.1227x over previous
#include <cuda_runtime.h>
#include <cuda_bf16.h>
#include <cuda_fp16.h>
#include <cstdint>

#define CDIM 1024
#define CS   2048
#define CB   4
#define NH   16
#define HD   64
#define LAT  128
#define QR   256
#define MTOT (CB*CS)   // 8192 tokens

// -------- scratch (static device globals; no runtime allocation) --------
__device__ float g_kvlat[(size_t)MTOT * LAT];        //  4 MB
__device__ float g_qlat [(size_t)MTOT * QR];         //  8 MB
__device__ float g_q    [(size_t)MTOT * CDIM];       // 32 MB
__device__ float g_ctx  [(size_t)MTOT * CDIM];       // 32 MB
__device__ __half g_kf16[(size_t)MTOT * CDIM];       // 16 MB  K (fp16)
__device__ __half g_vf16[(size_t)MTOT * CDIM];       // 16 MB  V (fp16)

// ---------------------------------------------------------------
// common helpers
// ---------------------------------------------------------------
__device__ __forceinline__ void mma_bf16(float d[4], const uint32_t a[4],
                                         const uint32_t b[2])
{
    asm volatile(
        "mma.sync.aligned.m16n8k16.row.col.f32.bf16.bf16.f32 "
        "{%0,%1,%2,%3}, {%4,%5,%6,%7}, {%8,%9}, {%0,%1,%2,%3};\n"
        : "+f"(d[0]), "+f"(d[1]), "+f"(d[2]), "+f"(d[3])
        : "r"(a[0]), "r"(a[1]), "r"(a[2]), "r"(a[3]),
          "r"(b[0]), "r"(b[1]));
}

__device__ __forceinline__ void mma_f16(float d[4], const uint32_t a[4],
                                        const uint32_t b[2])
{
    asm volatile(
        "mma.sync.aligned.m16n8k16.row.col.f32.f16.f16.f32 "
        "{%0,%1,%2,%3}, {%4,%5,%6,%7}, {%8,%9}, {%0,%1,%2,%3};\n"
        : "+f"(d[0]), "+f"(d[1]), "+f"(d[2]), "+f"(d[3])
        : "r"(a[0]), "r"(a[1]), "r"(a[2]), "r"(a[3]),
          "r"(b[0]), "r"(b[1]));
}

__device__ __forceinline__ uint32_t pack_bf16(float lo, float hi)
{
    uint32_t r;
    asm("cvt.rn.bf16x2.f32 %0, %2, %1;" : "=r"(r) : "f"(lo), "f"(hi));
    return r;
}

__device__ __forceinline__ uint32_t pack_f16(float lo, float hi)
{
    uint32_t r;
    asm("cvt.rn.f16x2.f32 %0, %2, %1;" : "=r"(r) : "f"(lo), "f"(hi));
    return r;
}

__device__ __forceinline__ uint32_t hpair(__nv_bfloat16 lo, __nv_bfloat16 hi)
{
    __nv_bfloat162 v;
    v.x = lo; v.y = hi;
    return *(uint32_t*)&v;
}

__device__ __forceinline__ void ldsm_x4(uint32_t r[4], const void* p)
{
    uint32_t a = (uint32_t)__cvta_generic_to_shared(p);
    asm volatile("ldmatrix.sync.aligned.m8n8.x4.shared.b16 {%0,%1,%2,%3}, [%4];"
                 : "=r"(r[0]), "=r"(r[1]), "=r"(r[2]), "=r"(r[3]) : "r"(a));
}

__device__ __forceinline__ void ldsm_x4_t(uint32_t r[4], const void* p)
{
    uint32_t a = (uint32_t)__cvta_generic_to_shared(p);
    asm volatile("ldmatrix.sync.aligned.m8n8.x4.trans.shared.b16 {%0,%1,%2,%3}, [%4];"
                 : "=r"(r[0]), "=r"(r[1]), "=r"(r[2]), "=r"(r[3]) : "r"(a));
}

__device__ __forceinline__ void cp_async16(void* s, const void* g)
{
    uint32_t sa = (uint32_t)__cvta_generic_to_shared(s);
    asm volatile("cp.async.cg.shared.global [%0], [%1], 16;" :: "r"(sa), "l"(g));
}

// ---------------------------------------------------------------
// Tensor-core GEMM with bf16 hi/lo 3-pass split (fp32-accurate),
// double-buffered smem: one __syncthreads per BK-iter; the fp32->bf16
// conversion of tile t+1 overlaps other warps' MMAs on tile t.
// MODE 0: C = A@B + bias (fp32).
// MODE 1: N==2048; cols [0,1024) -> P1 = K fp16; cols [1024,2048) -> P2 = V fp16.
// MODE 2: fused dual projection: block cols [0,128) -> C (kvlat);
//         cols [128,384) -> P3 (qlat) with B2=P1, bias2=P2. grid.x = 3.
// ---------------------------------------------------------------
#define APITCH 40
#define BPITCH 136

template<int MODE>
__global__ __launch_bounds__(256, 1) void hgemm_bias_t(
    const float* __restrict__ A, const float* __restrict__ B,
    const float* __restrict__ bias, float* __restrict__ C,
    void* __restrict__ P1, void* __restrict__ P2, void* __restrict__ P3,
    int M, int N, int K)
{
    __shared__ __align__(16) __nv_bfloat16 Ahs[2][128 * APITCH];
    __shared__ __align__(16) __nv_bfloat16 Als[2][128 * APITCH];
    __shared__ __align__(16) __nv_bfloat16 Bhs[2][32 * BPITCH];
    __shared__ __align__(16) __nv_bfloat16 Bls[2][32 * BPITCH];

    const int tid  = threadIdx.x;
    const int w    = tid >> 5;
    const int lane = tid & 31;
    const int wm   = w >> 2;
    const int wn   = w & 3;
    const int m0   = wm * 64;
    const int n0   = wn * 32;
    const int row0 = blockIdx.y * 128;
    const int col0 = blockIdx.x * 128;

    // per-block operand selection (MODE 2 fuses two projections)
    const float* Bp   = B;
    const float* bip  = bias;
    float*       Cp   = C;
    int Nl = N, cl = col0;
    if (MODE == 2) {
        if (col0 < LAT) { Nl = LAT; cl = col0; }
        else {
            Bp  = (const float*)P1;
            bip = (const float*)P2;
            Cp  = (float*)P3;
            Nl  = QR;
            cl  = col0 - LAT;
        }
    }

    float Cacc[4][4][4] = {};
    float4 aR[4], bR[4];

    auto ldTiles = [&](int k0) {
#pragma unroll
        for (int i = 0; i < 4; i++) {
            int f = tid + i * 256;
            int r = f >> 3, c = (f & 7) << 2;
            aR[i] = *(const float4*)(A + (size_t)(row0 + r) * K + k0 + c);
        }
#pragma unroll
        for (int i = 0; i < 4; i++) {
            int f = tid + i * 256;
            int r = f >> 5, c = (f & 31) << 2;
            bR[i] = *(const float4*)(Bp + (size_t)(k0 + r) * Nl + cl + c);
        }
    };

    auto stTiles = [&](int buf) {
#pragma unroll
        for (int i = 0; i < 4; i++) {
            int f = tid + i * 256;
            int r = f >> 3, c = (f & 7) << 2;
            float v[4] = {aR[i].x, aR[i].y, aR[i].z, aR[i].w};
#pragma unroll
            for (int j = 0; j < 2; j++) {
                __nv_bfloat16 h0 = __float2bfloat16(v[2 * j]);
                __nv_bfloat16 h1 = __float2bfloat16(v[2 * j + 1]);
                *(uint32_t*)&Ahs[buf][r * APITCH + c + 2 * j] = hpair(h0, h1);
                *(uint32_t*)&Als[buf][r * APITCH + c + 2 * j] =
                    hpair(__float2bfloat16(v[2 * j]     - __bfloat162float(h0)),
                          __float2bfloat16(v[2 * j + 1] - __bfloat162float(h1)));
            }
        }
#pragma unroll
        for (int i = 0; i < 4; i++) {
            int f = tid + i * 256;
            int r = f >> 5, c = (f & 31) << 2;
            float v[4] = {bR[i].x, bR[i].y, bR[i].z, bR[i].w};
#pragma unroll
            for (int j = 0; j < 2; j++) {
                __nv_bfloat16 h0 = __float2bfloat16(v[2 * j]);
                __nv_bfloat16 h1 = __float2bfloat16(v[2 * j + 1]);
                *(uint32_t*)&Bhs[buf][r * BPITCH + c + 2 * j] = hpair(h0, h1);
                *(uint32_t*)&Bls[buf][r * BPITCH + c + 2 * j] =
                    hpair(__float2bfloat16(v[2 * j]     - __bfloat162float(h0)),
                          __float2bfloat16(v[2 * j + 1] - __bfloat162float(h1)));
            }
        }
    };

    ldTiles(0);
    stTiles(0);
    __syncthreads();

    const int nk = K >> 5;
    for (int it = 0; it < nk; it++) {
        const int k0 = (it + 1) << 5;
        const bool more = k0 < K;
        const int buf = it & 1;
        if (more) ldTiles(k0);

#pragma unroll
        for (int ks = 0; ks < 2; ks++) {
            uint32_t Af[4][4], Alf[4][4];
#pragma unroll
            for (int mi = 0; mi < 4; mi++) {
                int idx = (m0 + mi * 16 + (lane & 15)) * APITCH
                        + ks * 16 + ((lane >> 4) << 3);
                ldsm_x4(Af[mi],  &Ahs[buf][idx]);
                ldsm_x4(Alf[mi], &Als[buf][idx]);
            }
            uint32_t Bf[4][2], Blf[4][2];
#pragma unroll
            for (int nj = 0; nj < 2; nj++) {
                int rrow = ks * 16 + ((lane >> 3) & 1) * 8 + (lane & 7);
                int ccol = n0 + nj * 16 + ((lane >> 4) << 3);
                uint32_t t4[4];
                ldsm_x4_t(t4, &Bhs[buf][rrow * BPITCH + ccol]);
                Bf[nj * 2][0] = t4[0]; Bf[nj * 2][1] = t4[1];
                Bf[nj * 2 + 1][0] = t4[2]; Bf[nj * 2 + 1][1] = t4[3];
                ldsm_x4_t(t4, &Bls[buf][rrow * BPITCH + ccol]);
                Blf[nj * 2][0] = t4[0]; Blf[nj * 2][1] = t4[1];
                Blf[nj * 2 + 1][0] = t4[2]; Blf[nj * 2 + 1][1] = t4[3];
            }
#pragma unroll
            for (int mi = 0; mi < 4; mi++)
#pragma unroll
                for (int nf = 0; nf < 4; nf++) {
                    mma_bf16(Cacc[mi][nf], Af[mi],  Bf[nf]);
                    mma_bf16(Cacc[mi][nf], Af[mi],  Blf[nf]);
                    mma_bf16(Cacc[mi][nf], Alf[mi], Bf[nf]);
                }
        }
        if (more) stTiles(buf ^ 1);
        __syncthreads();
    }

    // ---- epilogue ----
    const int g = lane >> 2, t = lane & 3;
#pragma unroll
    for (int mi = 0; mi < 4; mi++) {
#pragma unroll
        for (int nf = 0; nf < 4; nf++) {
            int gr = row0 + m0 + mi * 16 + g;
            int gc = cl + n0 + nf * 8 + 2 * t;
            float b0 = bip[gc], b1 = bip[gc + 1];
            float v00 = Cacc[mi][nf][0] + b0, v01 = Cacc[mi][nf][1] + b1;
            float v10 = Cacc[mi][nf][2] + b0, v11 = Cacc[mi][nf][3] + b1;
            if (MODE != 1) {
                float2 u0 = {v00, v01};
                float2 u1 = {v10, v11};
                *(float2*)&Cp[(size_t)gr * Nl + gc] = u0;
                *(float2*)&Cp[(size_t)(gr + 8) * Nl + gc] = u1;
            } else {
                if (col0 < 1024) {   // K plane (fp16)
                    __half* Kout = (__half*)P1;
                    *(uint32_t*)&Kout[(size_t)gr * CDIM + gc] = pack_f16(v00, v01);
                    *(uint32_t*)&Kout[(size_t)(gr + 8) * CDIM + gc] = pack_f16(v10, v11);
                } else {             // V plane (fp16)
                    __half* Vout = (__half*)P2;
                    int vc = gc - 1024;
                    *(uint32_t*)&Vout[(size_t)gr * CDIM + vc] = pack_f16(v00, v01);
                    *(uint32_t*)&Vout[(size_t)(gr + 8) * CDIM + vc] = pack_f16(v10, v11);
                }
            }
        }
    }
}

// ---------------------------------------------------------------
// Causal flash attention v4 (fp16, single V plane): pre-split fp16 K/V,
// cp.async double-buffered tiles, ldmatrix for QK and PV fragments,
// exp2-domain softmax, longest-CTA-first scheduling.
// grid (S/128, B*H), 256 threads. Dynamic smem 2*2*64*72*2 = 36864 B.
// ---------------------------------------------------------------
#define FPITCH 72
#define TILE_E (64 * FPITCH)

__global__ __launch_bounds__(256) void flash_attn_mma4(
    const float* __restrict__ Qm,
    const __half* __restrict__ Kfg,
    const __half* __restrict__ Vfg,
    float* __restrict__ ctx)
{
    extern __shared__ __half sm[];

    const int bh = blockIdx.y;
    const int b  = bh >> 4;
    const int h  = bh & 15;
    const int q0 = (gridDim.x - 1 - blockIdx.x) * 128;  // longest first
    const int tid  = threadIdx.x;
    const int w    = tid >> 5;
    const int lane = tid & 31;
    const int g    = lane >> 2;
    const int t    = lane & 3;
    const int qb   = q0 + w * 16;

    // ---- Q fragments fp16 (scale * log2e folded) ----
    uint32_t Qf[4][4];
    {
        const float* q0p = Qm + ((size_t)(b * CS + qb + g)) * CDIM + h * HD;
        const float* q1p = q0p + 8 * (size_t)CDIM;
        const float sc = 0.125f * 1.4426950408889634f;
#pragma unroll
        for (int kk = 0; kk < 4; kk++) {
            int c = kk * 16 + 2 * t;
            Qf[kk][0] = pack_f16(q0p[c]     * sc, q0p[c + 1] * sc);
            Qf[kk][1] = pack_f16(q1p[c]     * sc, q1p[c + 1] * sc);
            Qf[kk][2] = pack_f16(q0p[c + 8] * sc, q0p[c + 9] * sc);
            Qf[kk][3] = pack_f16(q1p[c + 8] * sc, q1p[c + 9] * sc);
        }
    }

    float O[8][4];
#pragma unroll
    for (int i = 0; i < 8; i++)
#pragma unroll
        for (int j = 0; j < 4; j++) O[i][j] = 0.f;
    float m0 = -1e30f, m1 = -1e30f, l0 = 0.f, l1 = 0.f;

    const int nkt = (q0 + 128) / 64;

    auto loadTile = [&](int kt, int buf) {
        __half* bs = sm + buf * 2 * TILE_E;
        const size_t rowbase = ((size_t)(b * CS + kt * 64)) * CDIM + h * HD;
#pragma unroll
        for (int i = 0; i < 4; i++) {
            int id = tid + i * 256;        // 0..1023
            int plane = id >> 9;
            int rem = id & 511;
            int r = rem >> 3;
            int c = (rem & 7) << 3;
            const __half* gp = (plane == 0 ? Kfg : Vfg)
                + rowbase + (size_t)r * CDIM + c;
            cp_async16(bs + plane * TILE_E + r * FPITCH + c, gp);
        }
        asm volatile("cp.async.commit_group;" ::: "memory");
    };

    loadTile(0, 0);

    for (int kt = 0; kt < nkt; kt++) {
        const int buf = kt & 1;
        if (kt + 1 < nkt) {
            loadTile(kt + 1, buf ^ 1);
            asm volatile("cp.async.wait_group 1;" ::: "memory");
        } else {
            asm volatile("cp.async.wait_group 0;" ::: "memory");
        }
        __syncthreads();

        if (kt * 64 <= qb + 15) {
            const __half* Ks = sm + buf * 2 * TILE_E;
            const __half* Vs = Ks + TILE_E;

            // ---- S = Q K^T  (K fragments via ldmatrix, rows = keys) ----
            float S[8][4];
#pragma unroll
            for (int j = 0; j < 8; j++) {
                S[j][0] = S[j][1] = S[j][2] = S[j][3] = 0.f;
#pragma unroll
                for (int kkp = 0; kkp < 2; kkp++) {
                    uint32_t t4[4];
                    const __half* kr = &Ks[(j * 8 + (lane & 7)) * FPITCH
                                           + kkp * 32 + ((lane >> 3) << 3)];
                    ldsm_x4(t4, kr);
                    uint32_t b0[2] = {t4[0], t4[1]};
                    uint32_t b1[2] = {t4[2], t4[3]};
                    mma_f16(S[j], Qf[2 * kkp],     b0);
                    mma_f16(S[j], Qf[2 * kkp + 1], b1);
                }
            }
            // ---- causal mask ----
            if (kt * 64 + 63 > qb) {
#pragma unroll
                for (int j = 0; j < 8; j++) {
                    int key = kt * 64 + j * 8 + 2 * t;
                    if (key     > qb + g)     S[j][0] = -1e30f;
                    if (key + 1 > qb + g)     S[j][1] = -1e30f;
                    if (key     > qb + g + 8) S[j][2] = -1e30f;
                    if (key + 1 > qb + g + 8) S[j][3] = -1e30f;
                }
            }
            // ---- online softmax (base-2 domain) ----
            float rmax0 = -1e30f, rmax1 = -1e30f;
#pragma unroll
            for (int j = 0; j < 8; j++) {
                rmax0 = fmaxf(rmax0, fmaxf(S[j][0], S[j][1]));
                rmax1 = fmaxf(rmax1, fmaxf(S[j][2], S[j][3]));
            }
#pragma unroll
            for (int off = 1; off <= 2; off <<= 1) {
                rmax0 = fmaxf(rmax0, __shfl_xor_sync(0xffffffffu, rmax0, off));
                rmax1 = fmaxf(rmax1, __shfl_xor_sync(0xffffffffu, rmax1, off));
            }
            float mn0 = fmaxf(m0, rmax0), mn1 = fmaxf(m1, rmax1);
            float sc0 = exp2f(m0 - mn0), sc1 = exp2f(m1 - mn1);
            float ls0 = 0.f, ls1 = 0.f;
#pragma unroll
            for (int j = 0; j < 8; j++) {
                S[j][0] = exp2f(S[j][0] - mn0); ls0 += S[j][0];
                S[j][1] = exp2f(S[j][1] - mn0); ls0 += S[j][1];
                S[j][2] = exp2f(S[j][2] - mn1); ls1 += S[j][2];
                S[j][3] = exp2f(S[j][3] - mn1); ls1 += S[j][3];
            }
#pragma unroll
            for (int off = 1; off <= 2; off <<= 1) {
                ls0 += __shfl_xor_sync(0xffffffffu, ls0, off);
                ls1 += __shfl_xor_sync(0xffffffffu, ls1, off);
            }
            l0 = l0 * sc0 + ls0;
            l1 = l1 * sc1 + ls1;
            m0 = mn0; m1 = mn1;
#pragma unroll
            for (int nj = 0; nj < 8; nj++) {
                O[nj][0] *= sc0; O[nj][1] *= sc0;
                O[nj][2] *= sc1; O[nj][3] *= sc1;
            }
            // ---- O += P V  (P fp16; V fp16 single plane) ----
#pragma unroll
            for (int s = 0; s < 4; s++) {
                uint32_t Ah[4];
#pragma unroll
                for (int r = 0; r < 4; r++) {
                    int jt = 2 * s + (r >> 1);
                    Ah[r] = pack_f16(S[jt][(r & 1) * 2 + 0],
                                     S[jt][(r & 1) * 2 + 1]);
                }
                const int rrow = s * 16 + ((lane >> 3) & 1) * 8 + (lane & 7);
#pragma unroll
                for (int nt = 0; nt < 4; nt++) {
                    const int ccol = nt * 16 + ((lane >> 4) << 3);
                    uint32_t th[4];
                    ldsm_x4_t(th, &Vs[rrow * FPITCH + ccol]);
                    uint32_t Bh0[2] = {th[0], th[1]}, Bh1[2] = {th[2], th[3]};
                    mma_f16(O[nt * 2],     Ah, Bh0);
                    mma_f16(O[nt * 2 + 1], Ah, Bh1);
                }
            }
        }
        __syncthreads();
    }

    // ---- epilogue ----
    float inv0 = 1.f / l0, inv1 = 1.f / l1;
    float* op0 = ctx + ((size_t)(b * CS + qb + g)) * CDIM + h * HD;
    float* op1 = op0 + 8 * (size_t)CDIM;
#pragma unroll
    for (int nj = 0; nj < 8; nj++) {
        int c = nj * 8 + 2 * t;
        op0[c]     = O[nj][0] * inv0;
        op0[c + 1] = O[nj][1] * inv0;
        op1[c]     = O[nj][2] * inv1;
        op1[c + 1] = O[nj][3] * inv1;
    }
}

// ---------------------------------------------------------------
extern "C" void kernel_launch(void* const* d_in, const int* in_sizes, int n_in,
                              void* d_out, int out_size)
{
    const float* x      = (const float*)d_in[0];
    // d_in[1] = causal mask (tril), implemented analytically in flash_attn_mma4
    const float* w_kvc  = (const float*)d_in[2];
    const float* b_kvc  = (const float*)d_in[3];
    const float* w_kvu  = (const float*)d_in[4];
    const float* b_kvu  = (const float*)d_in[5];
    const float* w_qc   = (const float*)d_in[6];
    const float* b_qc   = (const float*)d_in[7];
    const float* w_qu   = (const float*)d_in[8];
    const float* b_qu   = (const float*)d_in[9];
    const float* w_o    = (const float*)d_in[10];
    const float* b_o    = (const float*)d_in[11];
    float* out = (float*)d_out;

    float *kvlat, *qlat, *Qm, *ctx;
    __half *kf, *vf;
    cudaGetSymbolAddress((void**)&kvlat, g_kvlat);
    cudaGetSymbolAddress((void**)&qlat,  g_qlat);
    cudaGetSymbolAddress((void**)&Qm,    g_q);
    cudaGetSymbolAddress((void**)&ctx,   g_ctx);
    cudaGetSymbolAddress((void**)&kf,    g_kf16);
    cudaGetSymbolAddress((void**)&vf,    g_vf16);

    static bool attr_set = false;
    if (!attr_set) {
        cudaFuncSetAttribute(flash_attn_mma4,
                             cudaFuncAttributeMaxDynamicSharedMemorySize,
                             2 * 2 * TILE_E * (int)sizeof(__half));
        attr_set = true;
    }

    // 1+3) fused: kv_latent = x@w_kvc + b_kvc  AND  q_lat = x@w_qc + b_qc
    hgemm_bias_t<2><<<dim3((LAT+QR)/128, MTOT/128), 256>>>(
        x, w_kvc, b_kvc, kvlat,
        (void*)w_qc, (void*)b_qc, (void*)qlat,
        MTOT, LAT, CDIM);
    // 2) K/V = split(kv_latent @ w_kvu + b_kvu)  -> fp16 planes
    hgemm_bias_t<1><<<dim3(2*CDIM/128, MTOT/128), 256>>>(
        kvlat, w_kvu, b_kvu, nullptr,
        (void*)kf, (void*)vf, nullptr,
        MTOT, 2*CDIM, LAT);
    // 4) Q = q_lat @ w_qu + b_qu                [8192,1024]
    hgemm_bias_t<0><<<dim3(CDIM/128, MTOT/128), 256>>>(
        qlat, w_qu, b_qu, Qm,
        nullptr, nullptr, nullptr,
        MTOT, CDIM, QR);
    // 5) causal flash attention (fp16 tensor cores) -> ctx
    flash_attn_mma4<<<dim3(CS/128, CB*NH), 256,
                      2 * 2 * TILE_E * (int)sizeof(__half)>>>(Qm, kf, vf, ctx);
    // 6) out = ctx @ w_o + b_o                  [8192,1024]
    hgemm_bias_t<0><<<dim3(CDIM/128, MTOT/128), 256>>>(
        ctx, w_o, b_o, out,
        nullptr, nullptr, nullptr,
        MTOT, CDIM, CDIM);
}

// round 15
// speedup vs baseline: 5.8116x; 1.0368x over previous
#include <cuda_runtime.h>
#include <cuda_bf16.h>
#include <cuda_fp16.h>
#include <cstdint>

#define CDIM 1024
#define CS   2048
#define CB   4
#define NH   16
#define HD   64
#define LAT  128
#define QR   256
#define MTOT (CB*CS)   // 8192 tokens

// -------- scratch (static device globals; no runtime allocation) --------
__device__ float g_kvlat[(size_t)MTOT * LAT];        //  4 MB
__device__ float g_qlat [(size_t)MTOT * QR];         //  8 MB
__device__ float g_q    [(size_t)MTOT * CDIM];       // 32 MB
__device__ float g_ctx  [(size_t)MTOT * CDIM];       // 32 MB
__device__ __half g_kf16[(size_t)MTOT * CDIM];       // 16 MB  K (fp16)
__device__ __half g_vf16[(size_t)MTOT * CDIM];       // 16 MB  V (fp16)

// ---------------------------------------------------------------
// common helpers
// ---------------------------------------------------------------
__device__ __forceinline__ void mma_bf16(float d[4], const uint32_t a[4],
                                         const uint32_t b[2])
{
    asm volatile(
        "mma.sync.aligned.m16n8k16.row.col.f32.bf16.bf16.f32 "
        "{%0,%1,%2,%3}, {%4,%5,%6,%7}, {%8,%9}, {%0,%1,%2,%3};\n"
        : "+f"(d[0]), "+f"(d[1]), "+f"(d[2]), "+f"(d[3])
        : "r"(a[0]), "r"(a[1]), "r"(a[2]), "r"(a[3]),
          "r"(b[0]), "r"(b[1]));
}

__device__ __forceinline__ void mma_f16(float d[4], const uint32_t a[4],
                                        const uint32_t b[2])
{
    asm volatile(
        "mma.sync.aligned.m16n8k16.row.col.f32.f16.f16.f32 "
        "{%0,%1,%2,%3}, {%4,%5,%6,%7}, {%8,%9}, {%0,%1,%2,%3};\n"
        : "+f"(d[0]), "+f"(d[1]), "+f"(d[2]), "+f"(d[3])
        : "r"(a[0]), "r"(a[1]), "r"(a[2]), "r"(a[3]),
          "r"(b[0]), "r"(b[1]));
}

__device__ __forceinline__ uint32_t pack_bf16(float lo, float hi)
{
    uint32_t r;
    asm("cvt.rn.bf16x2.f32 %0, %2, %1;" : "=r"(r) : "f"(lo), "f"(hi));
    return r;
}

__device__ __forceinline__ uint32_t pack_f16(float lo, float hi)
{
    uint32_t r;
    asm("cvt.rn.f16x2.f32 %0, %2, %1;" : "=r"(r) : "f"(lo), "f"(hi));
    return r;
}

__device__ __forceinline__ uint32_t hpair(__nv_bfloat16 lo, __nv_bfloat16 hi)
{
    __nv_bfloat162 v;
    v.x = lo; v.y = hi;
    return *(uint32_t*)&v;
}

__device__ __forceinline__ uint32_t hpair16(__half lo, __half hi)
{
    __half2 v;
    v.x = lo; v.y = hi;
    return *(uint32_t*)&v;
}

__device__ __forceinline__ void ldsm_x4(uint32_t r[4], const void* p)
{
    uint32_t a = (uint32_t)__cvta_generic_to_shared(p);
    asm volatile("ldmatrix.sync.aligned.m8n8.x4.shared.b16 {%0,%1,%2,%3}, [%4];"
                 : "=r"(r[0]), "=r"(r[1]), "=r"(r[2]), "=r"(r[3]) : "r"(a));
}

__device__ __forceinline__ void ldsm_x4_t(uint32_t r[4], const void* p)
{
    uint32_t a = (uint32_t)__cvta_generic_to_shared(p);
    asm volatile("ldmatrix.sync.aligned.m8n8.x4.trans.shared.b16 {%0,%1,%2,%3}, [%4];"
                 : "=r"(r[0]), "=r"(r[1]), "=r"(r[2]), "=r"(r[3]) : "r"(a));
}

__device__ __forceinline__ void cp_async16(void* s, const void* g)
{
    uint32_t sa = (uint32_t)__cvta_generic_to_shared(s);
    asm volatile("cp.async.cg.shared.global [%0], [%1], 16;" :: "r"(sa), "l"(g));
}

// ---------------------------------------------------------------
// Tensor-core GEMM, 128x128 CTA tile, BK=32, double-buffered smem.
// EXACT=1: bf16 hi/lo split of BOTH operands, 3 MMA passes (fp32-exact).
// EXACT=0: fp16, A hi/lo split, B single, 2 MMA passes (~2.8e-4 rel).
// MODE 0: C = A@B + bias (fp32).
// MODE 2: fused x-projections. block col 0 -> C (kvlat, N=LAT);
//         block cols [1,3) -> C2 = A2@B2 + bias2 (qlat, N2=QR). grid.x=3.
// MODE 3: fused KV-up + Q-up. block cols [0,16): A@B+bias, N=2048,
//         cols [0,1024)->KP fp16, [1024,2048)->VP fp16;
//         block cols [16,24): C2 = A2@B2+bias2 (Q, N2=1024, K2). grid.x=24.
// ---------------------------------------------------------------
#define APITCH 40
#define BPITCH 136

template<int MODE, int EXACT>
__global__ __launch_bounds__(256, 1) void hgemm_t(
    const float* __restrict__ A, const float* __restrict__ B,
    const float* __restrict__ bias, float* __restrict__ C,
    __half* __restrict__ KP, __half* __restrict__ VP,
    const float* __restrict__ A2, const float* __restrict__ B2,
    const float* __restrict__ bias2, float* __restrict__ C2,
    int N, int K, int N2, int K2)
{
    __shared__ __align__(16) __half Ahs[2][128 * APITCH];
    __shared__ __align__(16) __half Als[2][128 * APITCH];
    __shared__ __align__(16) __half Bhs[2][32 * BPITCH];
    __shared__ __align__(16) __half Bls[EXACT ? 2 : 1][EXACT ? 32 * BPITCH : 2];

    const int tid  = threadIdx.x;
    const int w    = tid >> 5;
    const int lane = tid & 31;
    const int wm   = w >> 2;
    const int wn   = w & 3;
    const int m0   = wm * 64;
    const int n0   = wn * 32;
    const int row0 = blockIdx.y * 128;
    const int col0 = blockIdx.x * 128;

    const float* Ap  = A;
    const float* Bp  = B;
    const float* bip = bias;
    float*       Cp  = C;
    int Nl = N, Kl = K, cl = col0;
    bool kvepi = false;
    if (MODE == 2) {
        if (col0 >= LAT) {
            Ap = A2; Bp = B2; bip = bias2; Cp = C2;
            Nl = N2; Kl = K2; cl = col0 - LAT;
        }
    } else if (MODE == 3) {
        if (col0 < 2048) {
            kvepi = true;
        } else {
            Ap = A2; Bp = B2; bip = bias2; Cp = C2;
            Nl = N2; Kl = K2; cl = col0 - 2048;
        }
    }

    float Cacc[4][4][4] = {};
    float4 aR[4], bR[4];

    auto ldTiles = [&](int k0) {
#pragma unroll
        for (int i = 0; i < 4; i++) {
            int f = tid + i * 256;
            int r = f >> 3, c = (f & 7) << 2;
            aR[i] = *(const float4*)(Ap + (size_t)(row0 + r) * Kl + k0 + c);
        }
#pragma unroll
        for (int i = 0; i < 4; i++) {
            int f = tid + i * 256;
            int r = f >> 5, c = (f & 31) << 2;
            bR[i] = *(const float4*)(Bp + (size_t)(k0 + r) * Nl + cl + c);
        }
    };

    auto stTiles = [&](int buf) {
#pragma unroll
        for (int i = 0; i < 4; i++) {
            int f = tid + i * 256;
            int r = f >> 3, c = (f & 7) << 2;
            float v[4] = {aR[i].x, aR[i].y, aR[i].z, aR[i].w};
#pragma unroll
            for (int j = 0; j < 2; j++) {
                if constexpr (EXACT) {
                    __nv_bfloat16 h0 = __float2bfloat16(v[2 * j]);
                    __nv_bfloat16 h1 = __float2bfloat16(v[2 * j + 1]);
                    *(uint32_t*)&Ahs[buf][r * APITCH + c + 2 * j] = hpair(h0, h1);
                    *(uint32_t*)&Als[buf][r * APITCH + c + 2 * j] =
                        hpair(__float2bfloat16(v[2 * j]     - __bfloat162float(h0)),
                              __float2bfloat16(v[2 * j + 1] - __bfloat162float(h1)));
                } else {
                    __half h0 = __float2half(v[2 * j]);
                    __half h1 = __float2half(v[2 * j + 1]);
                    *(uint32_t*)&Ahs[buf][r * APITCH + c + 2 * j] = hpair16(h0, h1);
                    *(uint32_t*)&Als[buf][r * APITCH + c + 2 * j] =
                        hpair16(__float2half(v[2 * j]     - __half2float(h0)),
                                __float2half(v[2 * j + 1] - __half2float(h1)));
                }
            }
        }
#pragma unroll
        for (int i = 0; i < 4; i++) {
            int f = tid + i * 256;
            int r = f >> 5, c = (f & 31) << 2;
            float v[4] = {bR[i].x, bR[i].y, bR[i].z, bR[i].w};
#pragma unroll
            for (int j = 0; j < 2; j++) {
                if constexpr (EXACT) {
                    __nv_bfloat16 h0 = __float2bfloat16(v[2 * j]);
                    __nv_bfloat16 h1 = __float2bfloat16(v[2 * j + 1]);
                    *(uint32_t*)&Bhs[buf][r * BPITCH + c + 2 * j] = hpair(h0, h1);
                    *(uint32_t*)&Bls[buf][r * BPITCH + c + 2 * j] =
                        hpair(__float2bfloat16(v[2 * j]     - __bfloat162float(h0)),
                              __float2bfloat16(v[2 * j + 1] - __bfloat162float(h1)));
                } else {
                    *(uint32_t*)&Bhs[buf][r * BPITCH + c + 2 * j] =
                        pack_f16(v[2 * j], v[2 * j + 1]);
                }
            }
        }
    };

    ldTiles(0);
    stTiles(0);
    __syncthreads();

    const int nk = Kl >> 5;
    for (int it = 0; it < nk; it++) {
        const int k0 = (it + 1) << 5;
        const bool more = k0 < Kl;
        const int buf = it & 1;
        if (more) ldTiles(k0);

#pragma unroll
        for (int ks = 0; ks < 2; ks++) {
            uint32_t Af[4][4], Alf[4][4];
#pragma unroll
            for (int mi = 0; mi < 4; mi++) {
                int idx = (m0 + mi * 16 + (lane & 15)) * APITCH
                        + ks * 16 + ((lane >> 4) << 3);
                ldsm_x4(Af[mi],  &Ahs[buf][idx]);
                ldsm_x4(Alf[mi], &Als[buf][idx]);
            }
            uint32_t Bf[4][2], Blf[4][2];
#pragma unroll
            for (int nj = 0; nj < 2; nj++) {
                int rrow = ks * 16 + ((lane >> 3) & 1) * 8 + (lane & 7);
                int ccol = n0 + nj * 16 + ((lane >> 4) << 3);
                uint32_t t4[4];
                ldsm_x4_t(t4, &Bhs[buf][rrow * BPITCH + ccol]);
                Bf[nj * 2][0] = t4[0]; Bf[nj * 2][1] = t4[1];
                Bf[nj * 2 + 1][0] = t4[2]; Bf[nj * 2 + 1][1] = t4[3];
                if constexpr (EXACT) {
                    ldsm_x4_t(t4, &Bls[buf][rrow * BPITCH + ccol]);
                    Blf[nj * 2][0] = t4[0]; Blf[nj * 2][1] = t4[1];
                    Blf[nj * 2 + 1][0] = t4[2]; Blf[nj * 2 + 1][1] = t4[3];
                }
            }
#pragma unroll
            for (int mi = 0; mi < 4; mi++)
#pragma unroll
                for (int nf = 0; nf < 4; nf++) {
                    if constexpr (EXACT) {
                        mma_bf16(Cacc[mi][nf], Af[mi],  Bf[nf]);
                        mma_bf16(Cacc[mi][nf], Af[mi],  Blf[nf]);
                        mma_bf16(Cacc[mi][nf], Alf[mi], Bf[nf]);
                    } else {
                        mma_f16(Cacc[mi][nf], Af[mi],  Bf[nf]);
                        mma_f16(Cacc[mi][nf], Alf[mi], Bf[nf]);
                    }
                }
        }
        if (more) stTiles(buf ^ 1);
        __syncthreads();
    }

    // ---- epilogue ----
    const int g = lane >> 2, t = lane & 3;
#pragma unroll
    for (int mi = 0; mi < 4; mi++) {
#pragma unroll
        for (int nf = 0; nf < 4; nf++) {
            int gr = row0 + m0 + mi * 16 + g;
            int gc = cl + n0 + nf * 8 + 2 * t;
            float b0 = bip[gc], b1 = bip[gc + 1];
            float v00 = Cacc[mi][nf][0] + b0, v01 = Cacc[mi][nf][1] + b1;
            float v10 = Cacc[mi][nf][2] + b0, v11 = Cacc[mi][nf][3] + b1;
            if (!kvepi) {
                float2 u0 = {v00, v01};
                float2 u1 = {v10, v11};
                *(float2*)&Cp[(size_t)gr * Nl + gc] = u0;
                *(float2*)&Cp[(size_t)(gr + 8) * Nl + gc] = u1;
            } else {
                if (gc < 1024) {     // K plane (fp16)
                    *(uint32_t*)&KP[(size_t)gr * CDIM + gc] = pack_f16(v00, v01);
                    *(uint32_t*)&KP[(size_t)(gr + 8) * CDIM + gc] = pack_f16(v10, v11);
                } else {             // V plane (fp16)
                    int vc = gc - 1024;
                    *(uint32_t*)&VP[(size_t)gr * CDIM + vc] = pack_f16(v00, v01);
                    *(uint32_t*)&VP[(size_t)(gr + 8) * CDIM + vc] = pack_f16(v10, v11);
                }
            }
        }
    }
}

// ---------------------------------------------------------------
// Causal flash attention v5 (fp16): pre-split fp16 K/V, cp.async
// double-buffered tiles, ldmatrix fragments, exp2-domain softmax,
// l computed by P*ones MMA (no scalar sum, no shuffles for l),
// longest-CTA-first scheduling.
// grid (S/128, B*H), 256 threads. Dynamic smem 2*2*64*72*2 = 36864 B.
// ---------------------------------------------------------------
#define FPITCH 72
#define TILE_E (64 * FPITCH)

__global__ __launch_bounds__(256) void flash_attn_mma5(
    const float* __restrict__ Qm,
    const __half* __restrict__ Kfg,
    const __half* __restrict__ Vfg,
    float* __restrict__ ctx)
{
    extern __shared__ __half sm[];

    const int bh = blockIdx.y;
    const int b  = bh >> 4;
    const int h  = bh & 15;
    const int q0 = (gridDim.x - 1 - blockIdx.x) * 128;  // longest first
    const int tid  = threadIdx.x;
    const int w    = tid >> 5;
    const int lane = tid & 31;
    const int g    = lane >> 2;
    const int t    = lane & 3;
    const int qb   = q0 + w * 16;

    // ---- Q fragments fp16 (scale * log2e folded) ----
    uint32_t Qf[4][4];
    {
        const float* q0p = Qm + ((size_t)(b * CS + qb + g)) * CDIM + h * HD;
        const float* q1p = q0p + 8 * (size_t)CDIM;
        const float sc = 0.125f * 1.4426950408889634f;
#pragma unroll
        for (int kk = 0; kk < 4; kk++) {
            int c = kk * 16 + 2 * t;
            Qf[kk][0] = pack_f16(q0p[c]     * sc, q0p[c + 1] * sc);
            Qf[kk][1] = pack_f16(q1p[c]     * sc, q1p[c + 1] * sc);
            Qf[kk][2] = pack_f16(q0p[c + 8] * sc, q0p[c + 9] * sc);
            Qf[kk][3] = pack_f16(q1p[c + 8] * sc, q1p[c + 9] * sc);
        }
    }

    float O[8][4];
#pragma unroll
    for (int i = 0; i < 8; i++)
#pragma unroll
        for (int j = 0; j < 4; j++) O[i][j] = 0.f;
    float Lac[4] = {0.f, 0.f, 0.f, 0.f};      // row-sums via P*ones MMA
    float m0 = -1e30f, m1 = -1e30f;
    const uint32_t ones2[2] = {0x3C003C00u, 0x3C003C00u};

    const int nkt = (q0 + 128) / 64;

    auto loadTile = [&](int kt, int buf) {
        __half* bs = sm + buf * 2 * TILE_E;
        const size_t rowbase = ((size_t)(b * CS + kt * 64)) * CDIM + h * HD;
#pragma unroll
        for (int i = 0; i < 4; i++) {
            int id = tid + i * 256;        // 0..1023
            int plane = id >> 9;
            int rem = id & 511;
            int r = rem >> 3;
            int c = (rem & 7) << 3;
            const __half* gp = (plane == 0 ? Kfg : Vfg)
                + rowbase + (size_t)r * CDIM + c;
            cp_async16(bs + plane * TILE_E + r * FPITCH + c, gp);
        }
        asm volatile("cp.async.commit_group;" ::: "memory");
    };

    loadTile(0, 0);

    for (int kt = 0; kt < nkt; kt++) {
        const int buf = kt & 1;
        if (kt + 1 < nkt) {
            loadTile(kt + 1, buf ^ 1);
            asm volatile("cp.async.wait_group 1;" ::: "memory");
        } else {
            asm volatile("cp.async.wait_group 0;" ::: "memory");
        }
        __syncthreads();

        if (kt * 64 <= qb + 15) {
            const __half* Ks = sm + buf * 2 * TILE_E;
            const __half* Vs = Ks + TILE_E;

            // ---- S = Q K^T ----
            float S[8][4];
#pragma unroll
            for (int j = 0; j < 8; j++) {
                S[j][0] = S[j][1] = S[j][2] = S[j][3] = 0.f;
#pragma unroll
                for (int kkp = 0; kkp < 2; kkp++) {
                    uint32_t t4[4];
                    const __half* kr = &Ks[(j * 8 + (lane & 7)) * FPITCH
                                           + kkp * 32 + ((lane >> 3) << 3)];
                    ldsm_x4(t4, kr);
                    uint32_t b0[2] = {t4[0], t4[1]};
                    uint32_t b1[2] = {t4[2], t4[3]};
                    mma_f16(S[j], Qf[2 * kkp],     b0);
                    mma_f16(S[j], Qf[2 * kkp + 1], b1);
                }
            }
            // ---- causal mask ----
            if (kt * 64 + 63 > qb) {
#pragma unroll
                for (int j = 0; j < 8; j++) {
                    int key = kt * 64 + j * 8 + 2 * t;
                    if (key     > qb + g)     S[j][0] = -1e30f;
                    if (key + 1 > qb + g)     S[j][1] = -1e30f;
                    if (key     > qb + g + 8) S[j][2] = -1e30f;
                    if (key + 1 > qb + g + 8) S[j][3] = -1e30f;
                }
            }
            // ---- online softmax (base-2 domain) ----
            float rmax0 = -1e30f, rmax1 = -1e30f;
#pragma unroll
            for (int j = 0; j < 8; j++) {
                rmax0 = fmaxf(rmax0, fmaxf(S[j][0], S[j][1]));
                rmax1 = fmaxf(rmax1, fmaxf(S[j][2], S[j][3]));
            }
#pragma unroll
            for (int off = 1; off <= 2; off <<= 1) {
                rmax0 = fmaxf(rmax0, __shfl_xor_sync(0xffffffffu, rmax0, off));
                rmax1 = fmaxf(rmax1, __shfl_xor_sync(0xffffffffu, rmax1, off));
            }
            float mn0 = fmaxf(m0, rmax0), mn1 = fmaxf(m1, rmax1);
            float sc0 = exp2f(m0 - mn0), sc1 = exp2f(m1 - mn1);
#pragma unroll
            for (int j = 0; j < 8; j++) {
                S[j][0] = exp2f(S[j][0] - mn0);
                S[j][1] = exp2f(S[j][1] - mn0);
                S[j][2] = exp2f(S[j][2] - mn1);
                S[j][3] = exp2f(S[j][3] - mn1);
            }
            m0 = mn0; m1 = mn1;
            Lac[0] *= sc0; Lac[1] *= sc0; Lac[2] *= sc1; Lac[3] *= sc1;
#pragma unroll
            for (int nj = 0; nj < 8; nj++) {
                O[nj][0] *= sc0; O[nj][1] *= sc0;
                O[nj][2] *= sc1; O[nj][3] *= sc1;
            }
            // ---- O += P V ; Lac += P * ones ----
#pragma unroll
            for (int s = 0; s < 4; s++) {
                uint32_t Ah[4];
#pragma unroll
                for (int r = 0; r < 4; r++) {
                    int jt = 2 * s + (r >> 1);
                    Ah[r] = pack_f16(S[jt][(r & 1) * 2 + 0],
                                     S[jt][(r & 1) * 2 + 1]);
                }
                mma_f16(Lac, Ah, ones2);
                const int rrow = s * 16 + ((lane >> 3) & 1) * 8 + (lane & 7);
#pragma unroll
                for (int nt = 0; nt < 4; nt++) {
                    const int ccol = nt * 16 + ((lane >> 4) << 3);
                    uint32_t th[4];
                    ldsm_x4_t(th, &Vs[rrow * FPITCH + ccol]);
                    uint32_t Bh0[2] = {th[0], th[1]}, Bh1[2] = {th[2], th[3]};
                    mma_f16(O[nt * 2],     Ah, Bh0);
                    mma_f16(O[nt * 2 + 1], Ah, Bh1);
                }
            }
        }
        __syncthreads();
    }

    // ---- epilogue (all columns of Lac rows are equal row-sums) ----
    float inv0 = 1.f / Lac[0], inv1 = 1.f / Lac[2];
    float* op0 = ctx + ((size_t)(b * CS + qb + g)) * CDIM + h * HD;
    float* op1 = op0 + 8 * (size_t)CDIM;
#pragma unroll
    for (int nj = 0; nj < 8; nj++) {
        int c = nj * 8 + 2 * t;
        op0[c]     = O[nj][0] * inv0;
        op0[c + 1] = O[nj][1] * inv0;
        op1[c]     = O[nj][2] * inv1;
        op1[c + 1] = O[nj][3] * inv1;
    }
}

// ---------------------------------------------------------------
extern "C" void kernel_launch(void* const* d_in, const int* in_sizes, int n_in,
                              void* d_out, int out_size)
{
    const float* x      = (const float*)d_in[0];
    // d_in[1] = causal mask (tril), implemented analytically in flash_attn_mma5
    const float* w_kvc  = (const float*)d_in[2];
    const float* b_kvc  = (const float*)d_in[3];
    const float* w_kvu  = (const float*)d_in[4];
    const float* b_kvu  = (const float*)d_in[5];
    const float* w_qc   = (const float*)d_in[6];
    const float* b_qc   = (const float*)d_in[7];
    const float* w_qu   = (const float*)d_in[8];
    const float* b_qu   = (const float*)d_in[9];
    const float* w_o    = (const float*)d_in[10];
    const float* b_o    = (const float*)d_in[11];
    float* out = (float*)d_out;

    float *kvlat, *qlat, *Qm, *ctx;
    __half *kf, *vf;
    cudaGetSymbolAddress((void**)&kvlat, g_kvlat);
    cudaGetSymbolAddress((void**)&qlat,  g_qlat);
    cudaGetSymbolAddress((void**)&Qm,    g_q);
    cudaGetSymbolAddress((void**)&ctx,   g_ctx);
    cudaGetSymbolAddress((void**)&kf,    g_kf16);
    cudaGetSymbolAddress((void**)&vf,    g_vf16);

    static bool attr_set = false;
    if (!attr_set) {
        cudaFuncSetAttribute(flash_attn_mma5,
                             cudaFuncAttributeMaxDynamicSharedMemorySize,
                             2 * 2 * TILE_E * (int)sizeof(__half));
        attr_set = true;
    }

    // 1) fused: kv_latent = x@w_kvc + b_kvc  AND  q_lat = x@w_qc + b_qc
    hgemm_t<2, 0><<<dim3((LAT + QR) / 128, MTOT / 128), 256>>>(
        x, w_kvc, b_kvc, kvlat,
        nullptr, nullptr,
        x, w_qc, b_qc, qlat,
        LAT, CDIM, QR, CDIM);
    // 2) fused: K/V = split(kv_latent@w_kvu + b_kvu) -> fp16 planes
    //    AND    Q   = q_lat@w_qu + b_qu              -> fp32
    hgemm_t<3, 0><<<dim3((2 * CDIM + CDIM) / 128, MTOT / 128), 256>>>(
        kvlat, w_kvu, b_kvu, nullptr,
        kf, vf,
        qlat, w_qu, b_qu, Qm,
        2 * CDIM, LAT, CDIM, QR);
    // 3) causal flash attention (fp16 tensor cores) -> ctx
    flash_attn_mma5<<<dim3(CS / 128, CB * NH), 256,
                      2 * 2 * TILE_E * (int)sizeof(__half)>>>(Qm, kf, vf, ctx);
    // 4) out = ctx @ w_o + b_o  (fp32-exact bf16 3-pass)
    hgemm_t<0, 1><<<dim3(CDIM / 128, MTOT / 128), 256>>>(
        ctx, w_o, b_o, out,
        nullptr, nullptr,
        nullptr, nullptr, nullptr, nullptr,
        CDIM, CDIM, 0, 0);
}

// round 16
// speedup vs baseline: 7.0882x; 1.2197x over previous
#include <cuda_runtime.h>
#include <cuda_bf16.h>
#include <cuda_fp16.h>
#include <cstdint>

#define CDIM 1024
#define CS   2048
#define CB   4
#define NH   16
#define HD   64
#define LAT  128
#define QR   256
#define MTOT (CB*CS)   // 8192 tokens

// -------- scratch (static device globals; no runtime allocation) --------
__device__ float g_kvlat[(size_t)MTOT * LAT];        //  4 MB
__device__ float g_qlat [(size_t)MTOT * QR];         //  8 MB
__device__ float g_q    [(size_t)MTOT * CDIM];       // 32 MB
__device__ float g_ctx  [(size_t)MTOT * CDIM];       // 32 MB
__device__ __half g_kf16[(size_t)MTOT * CDIM];       // 16 MB  K (fp16)
__device__ __half g_vf16[(size_t)MTOT * CDIM];       // 16 MB  V (fp16)

// ---------------------------------------------------------------
// common helpers
// ---------------------------------------------------------------
__device__ __forceinline__ void mma_f16(float d[4], const uint32_t a[4],
                                        const uint32_t b[2])
{
    asm volatile(
        "mma.sync.aligned.m16n8k16.row.col.f32.f16.f16.f32 "
        "{%0,%1,%2,%3}, {%4,%5,%6,%7}, {%8,%9}, {%0,%1,%2,%3};\n"
        : "+f"(d[0]), "+f"(d[1]), "+f"(d[2]), "+f"(d[3])
        : "r"(a[0]), "r"(a[1]), "r"(a[2]), "r"(a[3]),
          "r"(b[0]), "r"(b[1]));
}

__device__ __forceinline__ uint32_t pack_f16(float lo, float hi)
{
    uint32_t r;
    asm("cvt.rn.f16x2.f32 %0, %2, %1;" : "=r"(r) : "f"(lo), "f"(hi));
    return r;
}

__device__ __forceinline__ uint32_t hpair16(__half lo, __half hi)
{
    __half2 v;
    v.x = lo; v.y = hi;
    return *(uint32_t*)&v;
}

__device__ __forceinline__ void ldsm_x4(uint32_t r[4], const void* p)
{
    uint32_t a = (uint32_t)__cvta_generic_to_shared(p);
    asm volatile("ldmatrix.sync.aligned.m8n8.x4.shared.b16 {%0,%1,%2,%3}, [%4];"
                 : "=r"(r[0]), "=r"(r[1]), "=r"(r[2]), "=r"(r[3]) : "r"(a));
}

__device__ __forceinline__ void ldsm_x4_t(uint32_t r[4], const void* p)
{
    uint32_t a = (uint32_t)__cvta_generic_to_shared(p);
    asm volatile("ldmatrix.sync.aligned.m8n8.x4.trans.shared.b16 {%0,%1,%2,%3}, [%4];"
                 : "=r"(r[0]), "=r"(r[1]), "=r"(r[2]), "=r"(r[3]) : "r"(a));
}

__device__ __forceinline__ void cp_async16(void* s, const void* g)
{
    uint32_t sa = (uint32_t)__cvta_generic_to_shared(s);
    asm volatile("cp.async.cg.shared.global [%0], [%1], 16;" :: "r"(sa), "l"(g));
}

// ---------------------------------------------------------------
// Tensor-core GEMM, 128x128 CTA tile, BK=32, double-buffered smem.
// fp16, A hi/lo split (2 MMA passes), B single fp16 (~2.8e-4 rel).
// MODE 0: C = A@B + bias (fp32).
// MODE 2: fused x-projections. block col 0 -> C (kvlat, N=LAT);
//         block cols [1,3) -> C2 = A2@B2 + bias2 (qlat, N2=QR). grid.x=3.
// MODE 3: fused KV-up + Q-up. block cols [0,16): A@B+bias, N=2048,
//         cols [0,1024)->KP fp16, [1024,2048)->VP fp16;
//         block cols [16,24): C2 = A2@B2+bias2 (Q, N2=1024, K2). grid.x=24.
// ---------------------------------------------------------------
#define APITCH 40
#define BPITCH 136

template<int MODE>
__global__ __launch_bounds__(256, 1) void hgemm_t(
    const float* __restrict__ A, const float* __restrict__ B,
    const float* __restrict__ bias, float* __restrict__ C,
    __half* __restrict__ KP, __half* __restrict__ VP,
    const float* __restrict__ A2, const float* __restrict__ B2,
    const float* __restrict__ bias2, float* __restrict__ C2,
    int N, int K, int N2, int K2)
{
    __shared__ __align__(16) __half Ahs[2][128 * APITCH];
    __shared__ __align__(16) __half Als[2][128 * APITCH];
    __shared__ __align__(16) __half Bhs[2][32 * BPITCH];

    const int tid  = threadIdx.x;
    const int w    = tid >> 5;
    const int lane = tid & 31;
    const int wm   = w >> 2;
    const int wn   = w & 3;
    const int m0   = wm * 64;
    const int n0   = wn * 32;
    const int row0 = blockIdx.y * 128;
    const int col0 = blockIdx.x * 128;

    const float* Ap  = A;
    const float* Bp  = B;
    const float* bip = bias;
    float*       Cp  = C;
    int Nl = N, Kl = K, cl = col0;
    bool kvepi = false;
    if (MODE == 2) {
        if (col0 >= LAT) {
            Ap = A2; Bp = B2; bip = bias2; Cp = C2;
            Nl = N2; Kl = K2; cl = col0 - LAT;
        }
    } else if (MODE == 3) {
        if (col0 < 2048) {
            kvepi = true;
        } else {
            Ap = A2; Bp = B2; bip = bias2; Cp = C2;
            Nl = N2; Kl = K2; cl = col0 - 2048;
        }
    }

    float Cacc[4][4][4] = {};
    float4 aR[4], bR[4];

    auto ldTiles = [&](int k0) {
#pragma unroll
        for (int i = 0; i < 4; i++) {
            int f = tid + i * 256;
            int r = f >> 3, c = (f & 7) << 2;
            aR[i] = *(const float4*)(Ap + (size_t)(row0 + r) * Kl + k0 + c);
        }
#pragma unroll
        for (int i = 0; i < 4; i++) {
            int f = tid + i * 256;
            int r = f >> 5, c = (f & 31) << 2;
            bR[i] = *(const float4*)(Bp + (size_t)(k0 + r) * Nl + cl + c);
        }
    };

    auto stTiles = [&](int buf) {
#pragma unroll
        for (int i = 0; i < 4; i++) {
            int f = tid + i * 256;
            int r = f >> 3, c = (f & 7) << 2;
            float v[4] = {aR[i].x, aR[i].y, aR[i].z, aR[i].w};
#pragma unroll
            for (int j = 0; j < 2; j++) {
                __half h0 = __float2half(v[2 * j]);
                __half h1 = __float2half(v[2 * j + 1]);
                *(uint32_t*)&Ahs[buf][r * APITCH + c + 2 * j] = hpair16(h0, h1);
                *(uint32_t*)&Als[buf][r * APITCH + c + 2 * j] =
                    hpair16(__float2half(v[2 * j]     - __half2float(h0)),
                            __float2half(v[2 * j + 1] - __half2float(h1)));
            }
        }
#pragma unroll
        for (int i = 0; i < 4; i++) {
            int f = tid + i * 256;
            int r = f >> 5, c = (f & 31) << 2;
            float v[4] = {bR[i].x, bR[i].y, bR[i].z, bR[i].w};
#pragma unroll
            for (int j = 0; j < 2; j++) {
                *(uint32_t*)&Bhs[buf][r * BPITCH + c + 2 * j] =
                    pack_f16(v[2 * j], v[2 * j + 1]);
            }
        }
    };

    ldTiles(0);
    stTiles(0);
    __syncthreads();

    const int nk = Kl >> 5;
    for (int it = 0; it < nk; it++) {
        const int k0 = (it + 1) << 5;
        const bool more = k0 < Kl;
        const int buf = it & 1;
        if (more) ldTiles(k0);

#pragma unroll
        for (int ks = 0; ks < 2; ks++) {
            uint32_t Af[4][4], Alf[4][4];
#pragma unroll
            for (int mi = 0; mi < 4; mi++) {
                int idx = (m0 + mi * 16 + (lane & 15)) * APITCH
                        + ks * 16 + ((lane >> 4) << 3);
                ldsm_x4(Af[mi],  &Ahs[buf][idx]);
                ldsm_x4(Alf[mi], &Als[buf][idx]);
            }
            uint32_t Bf[4][2];
#pragma unroll
            for (int nj = 0; nj < 2; nj++) {
                int rrow = ks * 16 + ((lane >> 3) & 1) * 8 + (lane & 7);
                int ccol = n0 + nj * 16 + ((lane >> 4) << 3);
                uint32_t t4[4];
                ldsm_x4_t(t4, &Bhs[buf][rrow * BPITCH + ccol]);
                Bf[nj * 2][0] = t4[0]; Bf[nj * 2][1] = t4[1];
                Bf[nj * 2 + 1][0] = t4[2]; Bf[nj * 2 + 1][1] = t4[3];
            }
#pragma unroll
            for (int mi = 0; mi < 4; mi++)
#pragma unroll
                for (int nf = 0; nf < 4; nf++) {
                    mma_f16(Cacc[mi][nf], Af[mi],  Bf[nf]);
                    mma_f16(Cacc[mi][nf], Alf[mi], Bf[nf]);
                }
        }
        if (more) stTiles(buf ^ 1);
        __syncthreads();
    }

    // ---- epilogue ----
    const int g = lane >> 2, t = lane & 3;
#pragma unroll
    for (int mi = 0; mi < 4; mi++) {
#pragma unroll
        for (int nf = 0; nf < 4; nf++) {
            int gr = row0 + m0 + mi * 16 + g;
            int gc = cl + n0 + nf * 8 + 2 * t;
            float b0 = bip[gc], b1 = bip[gc + 1];
            float v00 = Cacc[mi][nf][0] + b0, v01 = Cacc[mi][nf][1] + b1;
            float v10 = Cacc[mi][nf][2] + b0, v11 = Cacc[mi][nf][3] + b1;
            if (!kvepi) {
                float2 u0 = {v00, v01};
                float2 u1 = {v10, v11};
                *(float2*)&Cp[(size_t)gr * Nl + gc] = u0;
                *(float2*)&Cp[(size_t)(gr + 8) * Nl + gc] = u1;
            } else {
                if (gc < 1024) {     // K plane (fp16)
                    *(uint32_t*)&KP[(size_t)gr * CDIM + gc] = pack_f16(v00, v01);
                    *(uint32_t*)&KP[(size_t)(gr + 8) * CDIM + gc] = pack_f16(v10, v11);
                } else {             // V plane (fp16)
                    int vc = gc - 1024;
                    *(uint32_t*)&VP[(size_t)gr * CDIM + vc] = pack_f16(v00, v01);
                    *(uint32_t*)&VP[(size_t)(gr + 8) * CDIM + vc] = pack_f16(v10, v11);
                }
            }
        }
    }
}

// ---------------------------------------------------------------
// Causal flash attention v5 (fp16): pre-split fp16 K/V, cp.async
// double-buffered tiles, ldmatrix fragments, exp2-domain softmax,
// l computed by P*ones MMA, longest-CTA-first scheduling,
// 2 CTAs/SM co-residency (launch_bounds min-blocks = 2).
// grid (S/128, B*H), 256 threads. Dynamic smem 2*2*64*72*2 = 36864 B.
// ---------------------------------------------------------------
#define FPITCH 72
#define TILE_E (64 * FPITCH)

__global__ __launch_bounds__(256, 2) void flash_attn_mma5(
    const float* __restrict__ Qm,
    const __half* __restrict__ Kfg,
    const __half* __restrict__ Vfg,
    float* __restrict__ ctx)
{
    extern __shared__ __half sm[];

    const int bh = blockIdx.y;
    const int b  = bh >> 4;
    const int h  = bh & 15;
    const int q0 = (gridDim.x - 1 - blockIdx.x) * 128;  // longest first
    const int tid  = threadIdx.x;
    const int w    = tid >> 5;
    const int lane = tid & 31;
    const int g    = lane >> 2;
    const int t    = lane & 3;
    const int qb   = q0 + w * 16;

    // ---- Q fragments fp16 (scale * log2e folded) ----
    uint32_t Qf[4][4];
    {
        const float* q0p = Qm + ((size_t)(b * CS + qb + g)) * CDIM + h * HD;
        const float* q1p = q0p + 8 * (size_t)CDIM;
        const float sc = 0.125f * 1.4426950408889634f;
#pragma unroll
        for (int kk = 0; kk < 4; kk++) {
            int c = kk * 16 + 2 * t;
            Qf[kk][0] = pack_f16(q0p[c]     * sc, q0p[c + 1] * sc);
            Qf[kk][1] = pack_f16(q1p[c]     * sc, q1p[c + 1] * sc);
            Qf[kk][2] = pack_f16(q0p[c + 8] * sc, q0p[c + 9] * sc);
            Qf[kk][3] = pack_f16(q1p[c + 8] * sc, q1p[c + 9] * sc);
        }
    }

    float O[8][4];
#pragma unroll
    for (int i = 0; i < 8; i++)
#pragma unroll
        for (int j = 0; j < 4; j++) O[i][j] = 0.f;
    float Lac[4] = {0.f, 0.f, 0.f, 0.f};      // row-sums via P*ones MMA
    float m0 = -1e30f, m1 = -1e30f;
    const uint32_t ones2[2] = {0x3C003C00u, 0x3C003C00u};

    const int nkt = (q0 + 128) / 64;

    auto loadTile = [&](int kt, int buf) {
        __half* bs = sm + buf * 2 * TILE_E;
        const size_t rowbase = ((size_t)(b * CS + kt * 64)) * CDIM + h * HD;
#pragma unroll
        for (int i = 0; i < 4; i++) {
            int id = tid + i * 256;        // 0..1023
            int plane = id >> 9;
            int rem = id & 511;
            int r = rem >> 3;
            int c = (rem & 7) << 3;
            const __half* gp = (plane == 0 ? Kfg : Vfg)
                + rowbase + (size_t)r * CDIM + c;
            cp_async16(bs + plane * TILE_E + r * FPITCH + c, gp);
        }
        asm volatile("cp.async.commit_group;" ::: "memory");
    };

    loadTile(0, 0);

    for (int kt = 0; kt < nkt; kt++) {
        const int buf = kt & 1;
        if (kt + 1 < nkt) {
            loadTile(kt + 1, buf ^ 1);
            asm volatile("cp.async.wait_group 1;" ::: "memory");
        } else {
            asm volatile("cp.async.wait_group 0;" ::: "memory");
        }
        __syncthreads();

        if (kt * 64 <= qb + 15) {
            const __half* Ks = sm + buf * 2 * TILE_E;
            const __half* Vs = Ks + TILE_E;

            // ---- S = Q K^T ----
            float S[8][4];
#pragma unroll
            for (int j = 0; j < 8; j++) {
                S[j][0] = S[j][1] = S[j][2] = S[j][3] = 0.f;
#pragma unroll
                for (int kkp = 0; kkp < 2; kkp++) {
                    uint32_t t4[4];
                    const __half* kr = &Ks[(j * 8 + (lane & 7)) * FPITCH
                                           + kkp * 32 + ((lane >> 3) << 3)];
                    ldsm_x4(t4, kr);
                    uint32_t b0[2] = {t4[0], t4[1]};
                    uint32_t b1[2] = {t4[2], t4[3]};
                    mma_f16(S[j], Qf[2 * kkp],     b0);
                    mma_f16(S[j], Qf[2 * kkp + 1], b1);
                }
            }
            // ---- causal mask ----
            if (kt * 64 + 63 > qb) {
#pragma unroll
                for (int j = 0; j < 8; j++) {
                    int key = kt * 64 + j * 8 + 2 * t;
                    if (key     > qb + g)     S[j][0] = -1e30f;
                    if (key + 1 > qb + g)     S[j][1] = -1e30f;
                    if (key     > qb + g + 8) S[j][2] = -1e30f;
                    if (key + 1 > qb + g + 8) S[j][3] = -1e30f;
                }
            }
            // ---- online softmax (base-2 domain) ----
            float rmax0 = -1e30f, rmax1 = -1e30f;
#pragma unroll
            for (int j = 0; j < 8; j++) {
                rmax0 = fmaxf(rmax0, fmaxf(S[j][0], S[j][1]));
                rmax1 = fmaxf(rmax1, fmaxf(S[j][2], S[j][3]));
            }
#pragma unroll
            for (int off = 1; off <= 2; off <<= 1) {
                rmax0 = fmaxf(rmax0, __shfl_xor_sync(0xffffffffu, rmax0, off));
                rmax1 = fmaxf(rmax1, __shfl_xor_sync(0xffffffffu, rmax1, off));
            }
            float mn0 = fmaxf(m0, rmax0), mn1 = fmaxf(m1, rmax1);
            float sc0 = exp2f(m0 - mn0), sc1 = exp2f(m1 - mn1);
#pragma unroll
            for (int j = 0; j < 8; j++) {
                S[j][0] = exp2f(S[j][0] - mn0);
                S[j][1] = exp2f(S[j][1] - mn0);
                S[j][2] = exp2f(S[j][2] - mn1);
                S[j][3] = exp2f(S[j][3] - mn1);
            }
            m0 = mn0; m1 = mn1;
            Lac[0] *= sc0; Lac[1] *= sc0; Lac[2] *= sc1; Lac[3] *= sc1;
#pragma unroll
            for (int nj = 0; nj < 8; nj++) {
                O[nj][0] *= sc0; O[nj][1] *= sc0;
                O[nj][2] *= sc1; O[nj][3] *= sc1;
            }
            // ---- O += P V ; Lac += P * ones ----
#pragma unroll
            for (int s = 0; s < 4; s++) {
                uint32_t Ah[4];
#pragma unroll
                for (int r = 0; r < 4; r++) {
                    int jt = 2 * s + (r >> 1);
                    Ah[r] = pack_f16(S[jt][(r & 1) * 2 + 0],
                                     S[jt][(r & 1) * 2 + 1]);
                }
                mma_f16(Lac, Ah, ones2);
                const int rrow = s * 16 + ((lane >> 3) & 1) * 8 + (lane & 7);
#pragma unroll
                for (int nt = 0; nt < 4; nt++) {
                    const int ccol = nt * 16 + ((lane >> 4) << 3);
                    uint32_t th[4];
                    ldsm_x4_t(th, &Vs[rrow * FPITCH + ccol]);
                    uint32_t Bh0[2] = {th[0], th[1]}, Bh1[2] = {th[2], th[3]};
                    mma_f16(O[nt * 2],     Ah, Bh0);
                    mma_f16(O[nt * 2 + 1], Ah, Bh1);
                }
            }
        }
        __syncthreads();
    }

    // ---- epilogue (all columns of Lac rows are equal row-sums) ----
    float inv0 = 1.f / Lac[0], inv1 = 1.f / Lac[2];
    float* op0 = ctx + ((size_t)(b * CS + qb + g)) * CDIM + h * HD;
    float* op1 = op0 + 8 * (size_t)CDIM;
#pragma unroll
    for (int nj = 0; nj < 8; nj++) {
        int c = nj * 8 + 2 * t;
        op0[c]     = O[nj][0] * inv0;
        op0[c + 1] = O[nj][1] * inv0;
        op1[c]     = O[nj][2] * inv1;
        op1[c + 1] = O[nj][3] * inv1;
    }
}

// ---------------------------------------------------------------
extern "C" void kernel_launch(void* const* d_in, const int* in_sizes, int n_in,
                              void* d_out, int out_size)
{
    const float* x      = (const float*)d_in[0];
    // d_in[1] = causal mask (tril), implemented analytically in flash_attn_mma5
    const float* w_kvc  = (const float*)d_in[2];
    const float* b_kvc  = (const float*)d_in[3];
    const float* w_kvu  = (const float*)d_in[4];
    const float* b_kvu  = (const float*)d_in[5];
    const float* w_qc   = (const float*)d_in[6];
    const float* b_qc   = (const float*)d_in[7];
    const float* w_qu   = (const float*)d_in[8];
    const float* b_qu   = (const float*)d_in[9];
    const float* w_o    = (const float*)d_in[10];
    const float* b_o    = (const float*)d_in[11];
    float* out = (float*)d_out;

    float *kvlat, *qlat, *Qm, *ctx;
    __half *kf, *vf;
    cudaGetSymbolAddress((void**)&kvlat, g_kvlat);
    cudaGetSymbolAddress((void**)&qlat,  g_qlat);
    cudaGetSymbolAddress((void**)&Qm,    g_q);
    cudaGetSymbolAddress((void**)&ctx,   g_ctx);
    cudaGetSymbolAddress((void**)&kf,    g_kf16);
    cudaGetSymbolAddress((void**)&vf,    g_vf16);

    static bool attr_set = false;
    if (!attr_set) {
        cudaFuncSetAttribute(flash_attn_mma5,
                             cudaFuncAttributeMaxDynamicSharedMemorySize,
                             2 * 2 * TILE_E * (int)sizeof(__half));
        attr_set = true;
    }

    // 1) fused: kv_latent = x@w_kvc + b_kvc  AND  q_lat = x@w_qc + b_qc
    hgemm_t<2><<<dim3((LAT + QR) / 128, MTOT / 128), 256>>>(
        x, w_kvc, b_kvc, kvlat,
        nullptr, nullptr,
        x, w_qc, b_qc, qlat,
        LAT, CDIM, QR, CDIM);
    // 2) fused: K/V = split(kv_latent@w_kvu + b_kvu) -> fp16 planes
    //    AND    Q   = q_lat@w_qu + b_qu              -> fp32
    hgemm_t<3><<<dim3((2 * CDIM + CDIM) / 128, MTOT / 128), 256>>>(
        kvlat, w_kvu, b_kvu, nullptr,
        kf, vf,
        qlat, w_qu, b_qu, Qm,
        2 * CDIM, LAT, CDIM, QR);
    // 3) causal flash attention (fp16 tensor cores) -> ctx
    flash_attn_mma5<<<dim3(CS / 128, CB * NH), 256,
                      2 * 2 * TILE_E * (int)sizeof(__half)>>>(Qm, kf, vf, ctx);
    // 4) out = ctx @ w_o + b_o  (fp16 A-split 2-pass)
    hgemm_t<0><<<dim3(CDIM / 128, MTOT / 128), 256>>>(
        ctx, w_o, b_o, out,
        nullptr, nullptr,
        nullptr, nullptr, nullptr, nullptr,
        CDIM, CDIM, 0, 0);
}